// round 7
// baseline (speedup 1.0000x reference)
#include <cuda_runtime.h>
#include <cuda_fp16.h>
#include <cstdint>

#define NR 8192
#define DC 1024

// ---------------------------------------------------------------------------
// Static device scratch. Split-fp16 tensors stored [rows, 2K]: hi | lo.
// ---------------------------------------------------------------------------
__device__ float  g_S[(size_t)NR * NR];                 // 256 MB logits
__device__ __half g_img2[(size_t)NR * 2 * DC];
__device__ __half g_tab2[(size_t)NR * 2 * DC];
__device__ __half g_w2[(size_t)6 * DC * 2 * DC];        // 6x W^T [1024,2048]
__device__ __half g_wo2[(size_t)2 * DC * 4 * DC];       // Wo^T [2048,4096]
__device__ __half g_qk2[(size_t)4 * NR * 2 * DC];       // q1,k1,q2,k2
__device__ __half g_vt2[(size_t)2 * DC * 2 * NR];       // v1^T,v2^T [1024,16384]
__device__ __half g_S2[(size_t)NR * NR];                // probs hi-only
__device__ __half g_fused2[(size_t)NR * 4 * DC];        // fused split [8192,4096]

// ---------------------------------------------------------------------------
// helpers
// ---------------------------------------------------------------------------
__device__ __forceinline__ uint32_t smem_u32(const void* p) {
    uint32_t a;
    asm("{ .reg .u64 t; cvta.to.shared.u64 t, %1; cvt.u32.u64 %0, t; }" : "=r"(a) : "l"(p));
    return a;
}
__device__ __forceinline__ void cp16(uint32_t d, const void* g) {
    asm volatile("cp.async.cg.shared.global [%0], [%1], 16;"
                 :: "r"(d), "l"(__cvta_generic_to_global(g)) : "memory");
}
__device__ __forceinline__ void ldm4(uint32_t* r, uint32_t a) {
    asm volatile("ldmatrix.sync.aligned.m8n8.x4.shared.b16 {%0,%1,%2,%3}, [%4];"
                 : "=r"(r[0]), "=r"(r[1]), "=r"(r[2]), "=r"(r[3]) : "r"(a));
}
__device__ __forceinline__ void mma16816(float* d, const uint32_t* a, const uint32_t* b) {
    asm("mma.sync.aligned.m16n8k16.row.col.f32.f16.f16.f32 "
        "{%0,%1,%2,%3}, {%4,%5,%6,%7}, {%8,%9}, {%0,%1,%2,%3};"
        : "+f"(d[0]), "+f"(d[1]), "+f"(d[2]), "+f"(d[3])
        : "r"(a[0]), "r"(a[1]), "r"(a[2]), "r"(a[3]), "r"(b[0]), "r"(b[1]));
}
__device__ __forceinline__ __half2 split_hi(float x0, float x1, __half2& lo) {
    __half h0 = __float2half_rn(x0), h1 = __float2half_rn(x1);
    lo = __halves2half2(__float2half_rn(x0 - __half2float(h0)),
                        __float2half_rn(x1 - __half2float(h1)));
    return __halves2half2(h0, h1);
}

// ---------------------------------------------------------------------------
// Split-fp16 NT GEMM:  C[M,N] = A[M,K] . B[N,K]^T
// PASSES=3: (Ahi,Bhi)+(Ahi,Blo)+(Alo,Bhi). PASSES=2: drop (Alo,Bhi).
// PASSES=1: (Ahi,Bhi).
// Tile 128x128xBK64, 128 threads (4 warps, each 64x64 register tile),
// cp.async 3-stage, ldmatrix fragment loads (8 ldm4 -> 32 MMA per k16).
// OUT_MODE: 0 = fp32 to Cf, 1 = split fp16 to Ch (hi at col, lo at col+lo_off)
// BIAS: 0 none, 1 per-column, 2 per-row
// ---------------------------------------------------------------------------
#define TPB 128
#define AST 144                       // 128B data + 16B pad (36 banks/row)
#define STG (128 * AST * 2)           // 36864 B per stage (A+B)
#define GSMEM (3 * STG)               // 110592 B

template <int OUT_MODE, int BIAS, int PASSES>
__global__ __launch_bounds__(TPB)
void hgemm3(const __half* __restrict__ A, const __half* __restrict__ B, int K,
            size_t ldA, size_t ldB,
            float* __restrict__ Cf, __half* __restrict__ Ch,
            int ldc, int lo_off, const float* __restrict__ bias)
{
    extern __shared__ char smc[];
    const uint32_t sb = smem_u32(smc);
    const int tid = threadIdx.x;
    const int wid = tid >> 5, lane = tid & 31;
    const int g = lane >> 2, t = lane & 3;
    const int wm = wid & 1, wn = wid >> 1;          // 2x2 warp grid, 64x64 each
    const int m0 = blockIdx.y * 128, n0 = blockIdx.x * 128;

    const int K64 = K >> 6;
    const int total = PASSES * K64;

    const int lr = tid >> 3;              // 0..15 (row base, step 16)
    const int lc  = (tid & 7) * 8;        // half offset within 64-col row
    const int lcB = (tid & 7) * 16;       // byte offset

    auto load_stage = [&](int s, int step) {
        if (step < total) {
            const int seg = step / K64, kk = step - seg * K64;
            const size_t ak = (size_t)((PASSES == 3 && seg == 2) ? K : 0) + (size_t)kk * 64;
            const size_t bk = (size_t)((PASSES >= 2 && seg == 1) ? K : 0) + (size_t)kk * 64;
            const __half* ga = A + (size_t)(m0 + lr) * ldA + ak + lc;
            const __half* gb = B + (size_t)(n0 + lr) * ldB + bk + lc;
            const uint32_t da = sb + s * STG + lr * AST + lcB;
            const uint32_t db = da + 128 * AST;
#pragma unroll
            for (int i = 0; i < 8; ++i) {
                cp16(da + i * 16 * AST, ga + (size_t)i * 16 * ldA);
                cp16(db + i * 16 * AST, gb + (size_t)i * 16 * ldB);
            }
        }
        asm volatile("cp.async.commit_group;" ::: "memory");
    };

    float acc[4][8][4];
#pragma unroll
    for (int i = 0; i < 4; ++i)
#pragma unroll
        for (int j = 0; j < 8; ++j)
#pragma unroll
            for (int r = 0; r < 4; ++r) acc[i][j][r] = 0.0f;

    // ldmatrix per-lane offsets within a stage
    const uint32_t aoff = (uint32_t)(wm * 64 + (lane & 15)) * AST + ((lane >> 4) << 4);
    const uint32_t boff = 128 * AST +
        (uint32_t)(wn * 64 + ((lane & 7) | ((lane >> 1) & 8))) * AST +
        (((lane >> 3) & 1) << 4);

    load_stage(0, 0);
    load_stage(1, 1);

    for (int step = 0; step < total; ++step) {
        asm volatile("cp.async.wait_group 1;" ::: "memory");
        __syncthreads();
        load_stage((step + 2) % 3, step + 2);

        const uint32_t sbase = sb + (step % 3) * STG;

#pragma unroll
        for (int kh = 0; kh < 4; ++kh) {            // four k16 pieces of BK=64
            const uint32_t ko = kh * 32;            // bytes
            uint32_t af[4][4], bf[8][2];
#pragma unroll
            for (int mt = 0; mt < 4; ++mt)
                ldm4(af[mt], sbase + aoff + (uint32_t)mt * 16 * AST + ko);
#pragma unroll
            for (int np = 0; np < 4; ++np) {
                uint32_t r[4];
                ldm4(r, sbase + boff + (uint32_t)np * 16 * AST + ko);
                bf[np * 2][0] = r[0];      bf[np * 2][1] = r[1];
                bf[np * 2 + 1][0] = r[2];  bf[np * 2 + 1][1] = r[3];
            }
#pragma unroll
            for (int mt = 0; mt < 4; ++mt)
#pragma unroll
                for (int nt = 0; nt < 8; ++nt)
                    mma16816(acc[mt][nt], af[mt], bf[nt]);
        }
    }

    // ---- epilogue ----
#pragma unroll
    for (int mt = 0; mt < 4; ++mt) {
        const int r0 = m0 + wm * 64 + mt * 16 + g;
        const int r1 = r0 + 8;
#pragma unroll
        for (int nt = 0; nt < 8; ++nt) {
            const int col = n0 + wn * 64 + nt * 8 + 2 * t;
            float v00 = acc[mt][nt][0], v01 = acc[mt][nt][1];
            float v10 = acc[mt][nt][2], v11 = acc[mt][nt][3];
            if (BIAS == 1) {
                const float b0 = bias[col], b1 = bias[col + 1];
                v00 += b0; v01 += b1; v10 += b0; v11 += b1;
            } else if (BIAS == 2) {
                const float b0 = bias[r0], b1 = bias[r1];
                v00 += b0; v01 += b0; v10 += b1; v11 += b1;
            }
            if (OUT_MODE == 0) {
                *reinterpret_cast<float2*>(&Cf[(size_t)r0 * ldc + col]) = make_float2(v00, v01);
                *reinterpret_cast<float2*>(&Cf[(size_t)r1 * ldc + col]) = make_float2(v10, v11);
            } else {
                __half2 lo0, lo1;
                __half2 hi0 = split_hi(v00, v01, lo0);
                __half2 hi1 = split_hi(v10, v11, lo1);
                __half2* p0 = reinterpret_cast<__half2*>(&Ch[(size_t)r0 * ldc + col]);
                __half2* p1 = reinterpret_cast<__half2*>(&Ch[(size_t)r1 * ldc + col]);
                p0[0] = hi0;  p0[lo_off / 2] = lo0;
                p1[0] = hi1;  p1[lo_off / 2] = lo1;
            }
        }
    }
}

// ---------------------------------------------------------------------------
// fp32 [R,C] -> split fp16 [R,2C]
// ---------------------------------------------------------------------------
__global__ __launch_bounds__(256)
void convert_split(const float* __restrict__ in, __half* __restrict__ out,
                   int C, size_t total)
{
    size_t i = ((size_t)blockIdx.x * 256 + threadIdx.x) * 4;
    if (i >= total) return;
    float4 v = *reinterpret_cast<const float4*>(&in[i]);
    size_t r = i / C;
    int c = (int)(i - r * C);
    __half2 lo0, lo1;
    __half2 hi0 = split_hi(v.x, v.y, lo0);
    __half2 hi1 = split_hi(v.z, v.w, lo1);
    __half* row = out + r * (2 * (size_t)C);
    *reinterpret_cast<__half2*>(&row[c])         = hi0;
    *reinterpret_cast<__half2*>(&row[c + 2])     = hi1;
    *reinterpret_cast<__half2*>(&row[C + c])     = lo0;
    *reinterpret_cast<__half2*>(&row[C + c + 2]) = lo1;
}

// ---------------------------------------------------------------------------
// All 7 weight transposes in ONE launch: in[R,C] -> split fp16 out[C,2R].
// ---------------------------------------------------------------------------
__global__ __launch_bounds__(256)
void weight_prep(const float* w0, const float* w1, const float* w2c,
                 const float* w3, const float* w4, const float* w5,
                 const float* w6,
                 __half* o0, __half* o1, __half* o2, __half* o3,
                 __half* o4, __half* o5, __half* o6)
{
    const float* src; __half* dst; int R, C;
    switch (blockIdx.z) {
        case 0: src = w0; dst = o0; R = DC; C = DC; break;
        case 1: src = w1; dst = o1; R = DC; C = DC; break;
        case 2: src = w2c; dst = o2; R = DC; C = DC; break;
        case 3: src = w3; dst = o3; R = DC; C = DC; break;
        case 4: src = w4; dst = o4; R = DC; C = DC; break;
        case 5: src = w5; dst = o5; R = DC; C = DC; break;
        default: src = w6; dst = o6; R = 2 * DC; C = 2 * DC; break;
    }
    const int bx = blockIdx.x * 32, by = blockIdx.y * 32;
    if (bx >= C || by >= R) return;

    __shared__ float tl[32][33];
    const int tx = threadIdx.x, ty = threadIdx.y;
#pragma unroll
    for (int j = ty; j < 32; j += 8)
        tl[j][tx] = src[(size_t)(by + j) * C + bx + tx];
    __syncthreads();
#pragma unroll
    for (int j = ty; j < 32; j += 8) {
        const float v = tl[tx][j];
        const __half h = __float2half_rn(v);
        const __half l = __float2half_rn(v - __half2float(h));
        __half* row = dst + (size_t)(bx + j) * (2 * (size_t)R);
        row[by + tx]     = h;
        row[R + by + tx] = l;
    }
}

// ---------------------------------------------------------------------------
// Row softmax: fp32 logits -> fp16 probs (hi only, compact [NR,NR])
// ---------------------------------------------------------------------------
__global__ __launch_bounds__(256)
void softmax_hi(const float* __restrict__ S, __half* __restrict__ S2)
{
    __shared__ float row[NR];
    __shared__ float red[256];
    const float* p = S + (size_t)blockIdx.x * NR;
    __half* o = S2 + (size_t)blockIdx.x * NR;
    const int tid = threadIdx.x;

    float lmax = -3.0e38f;
    for (int i = tid * 4; i < NR; i += 1024) {
        float4 v = *reinterpret_cast<const float4*>(&p[i]);
        *reinterpret_cast<float4*>(&row[i]) = v;
        lmax = fmaxf(lmax, fmaxf(fmaxf(v.x, v.y), fmaxf(v.z, v.w)));
    }
    red[tid] = lmax;
    __syncthreads();
#pragma unroll
    for (int s = 128; s > 0; s >>= 1) {
        if (tid < s) red[tid] = fmaxf(red[tid], red[tid + s]);
        __syncthreads();
    }
    const float bmax = red[0];
    __syncthreads();

    float lsum = 0.0f;
    for (int i = tid * 4; i < NR; i += 1024) {
        float4 v = *reinterpret_cast<float4*>(&row[i]);
        v.x = __expf(v.x - bmax); v.y = __expf(v.y - bmax);
        v.z = __expf(v.z - bmax); v.w = __expf(v.w - bmax);
        lsum += v.x + v.y + v.z + v.w;
        *reinterpret_cast<float4*>(&row[i]) = v;
    }
    red[tid] = lsum;
    __syncthreads();
#pragma unroll
    for (int s = 128; s > 0; s >>= 1) {
        if (tid < s) red[tid] += red[tid + s];
        __syncthreads();
    }
    const float inv = 1.0f / red[0];
    __syncthreads();

    for (int i = tid * 4; i < NR; i += 1024) {
        float4 v = *reinterpret_cast<float4*>(&row[i]);
        *reinterpret_cast<__half2*>(&o[i]) =
            __halves2half2(__float2half_rn(v.x * inv), __float2half_rn(v.y * inv));
        *reinterpret_cast<__half2*>(&o[i + 2]) =
            __halves2half2(__float2half_rn(v.z * inv), __float2half_rn(v.w * inv));
    }
}

// ---------------------------------------------------------------------------
// Launch sequence
// ---------------------------------------------------------------------------
extern "C" void kernel_launch(void* const* d_in, const int* in_sizes, int n_in,
                              void* d_out, int out_size)
{
    const float* img = (const float*)d_in[0];
    const float* tab = (const float*)d_in[1];
    const float* Wqi = (const float*)d_in[2];  const float* bqi = (const float*)d_in[3];
    const float* Wkt = (const float*)d_in[4];  const float* bkt = (const float*)d_in[5];
    const float* Wvt = (const float*)d_in[6];  const float* bvt = (const float*)d_in[7];
    const float* Wqt = (const float*)d_in[8];  const float* bqt = (const float*)d_in[9];
    const float* Wki = (const float*)d_in[10]; const float* bki = (const float*)d_in[11];
    const float* Wvi = (const float*)d_in[12]; const float* bvi = (const float*)d_in[13];
    const float* Wo  = (const float*)d_in[14]; const float* bo  = (const float*)d_in[15];
    float* out = (float*)d_out;

    cudaFuncSetAttribute(hgemm3<0,0,3>, cudaFuncAttributeMaxDynamicSharedMemorySize, GSMEM);
    cudaFuncSetAttribute(hgemm3<0,1,2>, cudaFuncAttributeMaxDynamicSharedMemorySize, GSMEM);
    cudaFuncSetAttribute(hgemm3<1,0,1>, cudaFuncAttributeMaxDynamicSharedMemorySize, GSMEM);
    cudaFuncSetAttribute(hgemm3<1,1,3>, cudaFuncAttributeMaxDynamicSharedMemorySize, GSMEM);
    cudaFuncSetAttribute(hgemm3<1,2,3>, cudaFuncAttributeMaxDynamicSharedMemorySize, GSMEM);

    float *S;
    __half *img2, *tab2, *w2, *wo2, *qk2, *vt2, *S2, *fused2;
    cudaGetSymbolAddress((void**)&S,      g_S);
    cudaGetSymbolAddress((void**)&img2,   g_img2);
    cudaGetSymbolAddress((void**)&tab2,   g_tab2);
    cudaGetSymbolAddress((void**)&w2,     g_w2);
    cudaGetSymbolAddress((void**)&wo2,    g_wo2);
    cudaGetSymbolAddress((void**)&qk2,    g_qk2);
    cudaGetSymbolAddress((void**)&vt2,    g_vt2);
    cudaGetSymbolAddress((void**)&S2,     g_S2);
    cudaGetSymbolAddress((void**)&fused2, g_fused2);

    const size_t W2SZ = (size_t)DC * 2 * DC;
    __half* wqi2 = w2 + 0 * W2SZ;  __half* wkt2 = w2 + 1 * W2SZ;
    __half* wvt2 = w2 + 2 * W2SZ;  __half* wqt2 = w2 + 3 * W2SZ;
    __half* wki2 = w2 + 4 * W2SZ;  __half* wvi2 = w2 + 5 * W2SZ;
    const size_t QK2 = (size_t)NR * 2 * DC;
    __half* q12 = qk2 + 0 * QK2;   __half* k12 = qk2 + 1 * QK2;
    __half* q22 = qk2 + 2 * QK2;   __half* k22 = qk2 + 3 * QK2;
    __half* v1t2 = vt2;            __half* v2t2 = vt2 + (size_t)DC * 2 * NR;

    // ---- launches 0-2: input conversions + combined weight prep ----
    const size_t tot = (size_t)NR * DC;
    convert_split<<<(unsigned)((tot / 4 + 255) / 256), 256>>>(img, img2, DC, tot);
    convert_split<<<(unsigned)((tot / 4 + 255) / 256), 256>>>(tab, tab2, DC, tot);
    weight_prep<<<dim3(64, 64, 7), dim3(32, 8)>>>(
        Wqi, Wkt, Wvt, Wqt, Wki, Wvi, Wo,
        wqi2, wkt2, wvt2, wqt2, wki2, wvi2, wo2);

    // ---- launches 3-8: projections (3-pass) ----
    dim3 gP(DC / 128, NR / 128);
    hgemm3<1,1,3><<<gP, TPB, GSMEM>>>(img2, wqi2, DC, 2*DC, 2*DC, nullptr, q12, 2*DC, DC, bqi);
    hgemm3<1,1,3><<<gP, TPB, GSMEM>>>(tab2, wkt2, DC, 2*DC, 2*DC, nullptr, k12, 2*DC, DC, bkt);
    hgemm3<1,1,3><<<gP, TPB, GSMEM>>>(tab2, wqt2, DC, 2*DC, 2*DC, nullptr, q22, 2*DC, DC, bqt);
    hgemm3<1,1,3><<<gP, TPB, GSMEM>>>(img2, wki2, DC, 2*DC, 2*DC, nullptr, k22, 2*DC, DC, bki);
    dim3 gV(NR / 128, DC / 128);
    hgemm3<1,2,3><<<gV, TPB, GSMEM>>>(wvt2, tab2, DC, 2*DC, 2*DC, nullptr, v1t2, 2*NR, NR, bvt);
    hgemm3<1,2,3><<<gV, TPB, GSMEM>>>(wvi2, img2, DC, 2*DC, 2*DC, nullptr, v2t2, 2*NR, NR, bvi);

    dim3 gS(NR / 128, NR / 128);
    dim3 gPV(DC / 128, NR / 128);

    // ---- branch 1: attended_tabular -> fused cols [1024,2048) ----
    hgemm3<0,0,3><<<gS, TPB, GSMEM>>>(q12, k12, DC, 2*DC, 2*DC, S, nullptr, NR, 0, nullptr);
    softmax_hi<<<NR, 256>>>(S, S2);
    hgemm3<1,0,1><<<gPV, TPB, GSMEM>>>(S2, v1t2, NR, NR, 2*NR, nullptr, fused2 + DC, 4*DC, 2*DC, nullptr);

    // ---- branch 2: attended_image -> fused cols [0,1024) ----
    hgemm3<0,0,3><<<gS, TPB, GSMEM>>>(q22, k22, DC, 2*DC, 2*DC, S, nullptr, NR, 0, nullptr);
    softmax_hi<<<NR, 256>>>(S, S2);
    hgemm3<1,0,1><<<gPV, TPB, GSMEM>>>(S2, v2t2, NR, NR, 2*NR, nullptr, fused2, 4*DC, 2*DC, nullptr);

    // ---- output projection (fp32 out, 2-pass) ----
    dim3 gO(2 * DC / 128, NR / 128);
    hgemm3<0,1,2><<<gO, TPB, GSMEM>>>(fused2, wo2, 2*DC, 4*DC, 4*DC, out, nullptr, 2*DC, 0, bo);
}

// round 8
// speedup vs baseline: 1.1319x; 1.1319x over previous
#include <cuda_runtime.h>
#include <cuda_fp16.h>
#include <cstdint>

#define NR 8192
#define DC 1024

// ---------------------------------------------------------------------------
// Static device scratch. Split-fp16 tensors stored [rows, 2K]: hi | lo.
// ---------------------------------------------------------------------------
__device__ float  g_S[(size_t)NR * NR];                 // 256 MB logits
__device__ __half g_img2[(size_t)NR * 2 * DC];
__device__ __half g_tab2[(size_t)NR * 2 * DC];
__device__ __half g_w2[(size_t)6 * DC * 2 * DC];        // 6x W^T [1024,2048]
__device__ __half g_wo2[(size_t)2 * DC * 4 * DC];       // Wo^T [2048,4096]
__device__ __half g_qk2[(size_t)4 * NR * 2 * DC];       // q1,k1,q2,k2
__device__ __half g_vt2[(size_t)2 * DC * 2 * NR];       // v1^T,v2^T [1024,16384]
__device__ __half g_S2[(size_t)NR * NR];                // probs hi-only
__device__ __half g_fused2[(size_t)NR * 4 * DC];        // fused split [8192,4096]

// ---------------------------------------------------------------------------
// helpers
// ---------------------------------------------------------------------------
__device__ __forceinline__ uint32_t smem_u32(const void* p) {
    uint32_t a;
    asm("{ .reg .u64 t; cvta.to.shared.u64 t, %1; cvt.u32.u64 %0, t; }" : "=r"(a) : "l"(p));
    return a;
}
__device__ __forceinline__ void cp16(uint32_t d, const void* g) {
    asm volatile("cp.async.cg.shared.global [%0], [%1], 16;"
                 :: "r"(d), "l"(__cvta_generic_to_global(g)) : "memory");
}
__device__ __forceinline__ void ldm4(uint32_t* r, uint32_t a) {
    asm volatile("ldmatrix.sync.aligned.m8n8.x4.shared.b16 {%0,%1,%2,%3}, [%4];"
                 : "=r"(r[0]), "=r"(r[1]), "=r"(r[2]), "=r"(r[3]) : "r"(a));
}
__device__ __forceinline__ void mma16816(float* d, const uint32_t* a, const uint32_t* b) {
    asm("mma.sync.aligned.m16n8k16.row.col.f32.f16.f16.f32 "
        "{%0,%1,%2,%3}, {%4,%5,%6,%7}, {%8,%9}, {%0,%1,%2,%3};"
        : "+f"(d[0]), "+f"(d[1]), "+f"(d[2]), "+f"(d[3])
        : "r"(a[0]), "r"(a[1]), "r"(a[2]), "r"(a[3]), "r"(b[0]), "r"(b[1]));
}
__device__ __forceinline__ __half2 split_hi(float x0, float x1, __half2& lo) {
    __half h0 = __float2half_rn(x0), h1 = __float2half_rn(x1);
    lo = __halves2half2(__float2half_rn(x0 - __half2float(h0)),
                        __float2half_rn(x1 - __half2float(h1)));
    return __halves2half2(h0, h1);
}

// ---------------------------------------------------------------------------
// Split-fp16 NT GEMM:  C[M,N] = A[M,K] . B[N,K]^T
// PASSES=3: (Ahi,Bhi)+(Ahi,Blo)+(Alo,Bhi). PASSES=2: drop (Alo,Bhi).
// PASSES=1: (Ahi,Bhi) only.
// Tile 128x128xBK64, 256 threads (8 warps 2x4, each 64x32 register tile),
// cp.async 3-stage, ldmatrix fragment loads.
// OUT_MODE: 0 = fp32 to Cf, 1 = split fp16 to Ch (hi at col, lo at col+lo_off)
// BIAS: 0 none, 1 per-column, 2 per-row
// ---------------------------------------------------------------------------
#define TPB 256
#define AST 144                       // 128B data + 16B pad (36 banks/row)
#define STG (128 * AST * 2)           // 36864 B per stage (A+B)
#define GSMEM (3 * STG)               // 110592 B

template <int OUT_MODE, int BIAS, int PASSES>
__global__ __launch_bounds__(TPB)
void hgemm3(const __half* __restrict__ A, const __half* __restrict__ B, int K,
            size_t ldA, size_t ldB,
            float* __restrict__ Cf, __half* __restrict__ Ch,
            int ldc, int lo_off, const float* __restrict__ bias)
{
    extern __shared__ char smc[];
    const uint32_t sb = smem_u32(smc);
    const int tid = threadIdx.x;
    const int wid = tid >> 5, lane = tid & 31;
    const int g = lane >> 2, t = lane & 3;
    const int wm = wid & 1, wn = wid >> 1;          // 2x4 warp grid, 64x32 each
    const int m0 = blockIdx.y * 128, n0 = blockIdx.x * 128;

    const int K64 = K >> 6;
    const int total = PASSES * K64;

    const int lr = tid >> 3;              // 0..31 (row base, step 32)
    const int lc  = (tid & 7) * 8;        // half offset within 64-col row
    const int lcB = (tid & 7) * 16;       // byte offset

    auto load_stage = [&](int s, int step) {
        if (step < total) {
            const int seg = step / K64, kk = step - seg * K64;
            const size_t ak = (size_t)((PASSES == 3 && seg == 2) ? K : 0) + (size_t)kk * 64;
            const size_t bk = (size_t)((PASSES >= 2 && seg == 1) ? K : 0) + (size_t)kk * 64;
            const __half* ga = A + (size_t)(m0 + lr) * ldA + ak + lc;
            const __half* gb = B + (size_t)(n0 + lr) * ldB + bk + lc;
            const uint32_t da = sb + s * STG + lr * AST + lcB;
            const uint32_t db = da + 128 * AST;
#pragma unroll
            for (int i = 0; i < 4; ++i) {
                cp16(da + i * 32 * AST, ga + (size_t)i * 32 * ldA);
                cp16(db + i * 32 * AST, gb + (size_t)i * 32 * ldB);
            }
        }
        asm volatile("cp.async.commit_group;" ::: "memory");
    };

    float acc[4][4][4];
#pragma unroll
    for (int i = 0; i < 4; ++i)
#pragma unroll
        for (int j = 0; j < 4; ++j)
#pragma unroll
            for (int r = 0; r < 4; ++r) acc[i][j][r] = 0.0f;

    // ldmatrix per-lane offsets within a stage
    const uint32_t aoff = (uint32_t)(wm * 64 + (lane & 15)) * AST + ((lane >> 4) << 4);
    const uint32_t boff = 128 * AST +
        (uint32_t)(wn * 32 + ((lane & 7) | ((lane >> 1) & 8))) * AST +
        (((lane >> 3) & 1) << 4);

    load_stage(0, 0);
    load_stage(1, 1);

    for (int step = 0; step < total; ++step) {
        asm volatile("cp.async.wait_group 1;" ::: "memory");
        __syncthreads();
        load_stage((step + 2) % 3, step + 2);

        const uint32_t sbase = sb + (step % 3) * STG;

#pragma unroll
        for (int kh = 0; kh < 4; ++kh) {            // four k16 pieces of BK=64
            const uint32_t ko = kh * 32;            // bytes
            uint32_t af[4][4], bf[4][2];
#pragma unroll
            for (int mt = 0; mt < 4; ++mt)
                ldm4(af[mt], sbase + aoff + (uint32_t)mt * 16 * AST + ko);
#pragma unroll
            for (int np = 0; np < 2; ++np) {
                uint32_t r[4];
                ldm4(r, sbase + boff + (uint32_t)np * 16 * AST + ko);
                bf[np * 2][0] = r[0];      bf[np * 2][1] = r[1];
                bf[np * 2 + 1][0] = r[2];  bf[np * 2 + 1][1] = r[3];
            }
#pragma unroll
            for (int mt = 0; mt < 4; ++mt)
#pragma unroll
                for (int nt = 0; nt < 4; ++nt)
                    mma16816(acc[mt][nt], af[mt], bf[nt]);
        }
    }

    // ---- epilogue ----
#pragma unroll
    for (int mt = 0; mt < 4; ++mt) {
        const int r0 = m0 + wm * 64 + mt * 16 + g;
        const int r1 = r0 + 8;
#pragma unroll
        for (int nt = 0; nt < 4; ++nt) {
            const int col = n0 + wn * 32 + nt * 8 + 2 * t;
            float v00 = acc[mt][nt][0], v01 = acc[mt][nt][1];
            float v10 = acc[mt][nt][2], v11 = acc[mt][nt][3];
            if (BIAS == 1) {
                const float b0 = bias[col], b1 = bias[col + 1];
                v00 += b0; v01 += b1; v10 += b0; v11 += b1;
            } else if (BIAS == 2) {
                const float b0 = bias[r0], b1 = bias[r1];
                v00 += b0; v01 += b0; v10 += b1; v11 += b1;
            }
            if (OUT_MODE == 0) {
                *reinterpret_cast<float2*>(&Cf[(size_t)r0 * ldc + col]) = make_float2(v00, v01);
                *reinterpret_cast<float2*>(&Cf[(size_t)r1 * ldc + col]) = make_float2(v10, v11);
            } else {
                __half2 lo0, lo1;
                __half2 hi0 = split_hi(v00, v01, lo0);
                __half2 hi1 = split_hi(v10, v11, lo1);
                __half2* p0 = reinterpret_cast<__half2*>(&Ch[(size_t)r0 * ldc + col]);
                __half2* p1 = reinterpret_cast<__half2*>(&Ch[(size_t)r1 * ldc + col]);
                p0[0] = hi0;  p0[lo_off / 2] = lo0;
                p1[0] = hi1;  p1[lo_off / 2] = lo1;
            }
        }
    }
}

// ---------------------------------------------------------------------------
// fp32 [R,C] -> split fp16 [R,2C]
// ---------------------------------------------------------------------------
__global__ __launch_bounds__(256)
void convert_split(const float* __restrict__ in, __half* __restrict__ out,
                   int C, size_t total)
{
    size_t i = ((size_t)blockIdx.x * 256 + threadIdx.x) * 4;
    if (i >= total) return;
    float4 v = *reinterpret_cast<const float4*>(&in[i]);
    size_t r = i / C;
    int c = (int)(i - r * C);
    __half2 lo0, lo1;
    __half2 hi0 = split_hi(v.x, v.y, lo0);
    __half2 hi1 = split_hi(v.z, v.w, lo1);
    __half* row = out + r * (2 * (size_t)C);
    *reinterpret_cast<__half2*>(&row[c])         = hi0;
    *reinterpret_cast<__half2*>(&row[c + 2])     = hi1;
    *reinterpret_cast<__half2*>(&row[C + c])     = lo0;
    *reinterpret_cast<__half2*>(&row[C + c + 2]) = lo1;
}

// ---------------------------------------------------------------------------
// All 7 weight transposes in ONE launch: in[R,C] -> split fp16 out[C,2R].
// ---------------------------------------------------------------------------
__global__ __launch_bounds__(256)
void weight_prep(const float* w0, const float* w1, const float* w2c,
                 const float* w3, const float* w4, const float* w5,
                 const float* w6,
                 __half* o0, __half* o1, __half* o2, __half* o3,
                 __half* o4, __half* o5, __half* o6)
{
    const float* src; __half* dst; int R, C;
    switch (blockIdx.z) {
        case 0: src = w0; dst = o0; R = DC; C = DC; break;
        case 1: src = w1; dst = o1; R = DC; C = DC; break;
        case 2: src = w2c; dst = o2; R = DC; C = DC; break;
        case 3: src = w3; dst = o3; R = DC; C = DC; break;
        case 4: src = w4; dst = o4; R = DC; C = DC; break;
        case 5: src = w5; dst = o5; R = DC; C = DC; break;
        default: src = w6; dst = o6; R = 2 * DC; C = 2 * DC; break;
    }
    const int bx = blockIdx.x * 32, by = blockIdx.y * 32;
    if (bx >= C || by >= R) return;

    __shared__ float tl[32][33];
    const int tx = threadIdx.x, ty = threadIdx.y;
#pragma unroll
    for (int j = ty; j < 32; j += 8)
        tl[j][tx] = src[(size_t)(by + j) * C + bx + tx];
    __syncthreads();
#pragma unroll
    for (int j = ty; j < 32; j += 8) {
        const float v = tl[tx][j];
        const __half h = __float2half_rn(v);
        const __half l = __float2half_rn(v - __half2float(h));
        __half* row = dst + (size_t)(bx + j) * (2 * (size_t)R);
        row[by + tx]     = h;
        row[R + by + tx] = l;
    }
}

// ---------------------------------------------------------------------------
// Row softmax: fp32 logits -> fp16 probs (hi only, compact [NR,NR])
// ---------------------------------------------------------------------------
__global__ __launch_bounds__(256)
void softmax_hi(const float* __restrict__ S, __half* __restrict__ S2)
{
    __shared__ float row[NR];
    __shared__ float red[256];
    const float* p = S + (size_t)blockIdx.x * NR;
    __half* o = S2 + (size_t)blockIdx.x * NR;
    const int tid = threadIdx.x;

    float lmax = -3.0e38f;
    for (int i = tid * 4; i < NR; i += 1024) {
        float4 v = *reinterpret_cast<const float4*>(&p[i]);
        *reinterpret_cast<float4*>(&row[i]) = v;
        lmax = fmaxf(lmax, fmaxf(fmaxf(v.x, v.y), fmaxf(v.z, v.w)));
    }
    red[tid] = lmax;
    __syncthreads();
#pragma unroll
    for (int s = 128; s > 0; s >>= 1) {
        if (tid < s) red[tid] = fmaxf(red[tid], red[tid + s]);
        __syncthreads();
    }
    const float bmax = red[0];
    __syncthreads();

    float lsum = 0.0f;
    for (int i = tid * 4; i < NR; i += 1024) {
        float4 v = *reinterpret_cast<float4*>(&row[i]);
        v.x = __expf(v.x - bmax); v.y = __expf(v.y - bmax);
        v.z = __expf(v.z - bmax); v.w = __expf(v.w - bmax);
        lsum += v.x + v.y + v.z + v.w;
        *reinterpret_cast<float4*>(&row[i]) = v;
    }
    red[tid] = lsum;
    __syncthreads();
#pragma unroll
    for (int s = 128; s > 0; s >>= 1) {
        if (tid < s) red[tid] += red[tid + s];
        __syncthreads();
    }
    const float inv = 1.0f / red[0];
    __syncthreads();

    for (int i = tid * 4; i < NR; i += 1024) {
        float4 v = *reinterpret_cast<float4*>(&row[i]);
        *reinterpret_cast<__half2*>(&o[i]) =
            __halves2half2(__float2half_rn(v.x * inv), __float2half_rn(v.y * inv));
        *reinterpret_cast<__half2*>(&o[i + 2]) =
            __halves2half2(__float2half_rn(v.z * inv), __float2half_rn(v.w * inv));
    }
}

// ---------------------------------------------------------------------------
// Launch sequence
// ---------------------------------------------------------------------------
extern "C" void kernel_launch(void* const* d_in, const int* in_sizes, int n_in,
                              void* d_out, int out_size)
{
    const float* img = (const float*)d_in[0];
    const float* tab = (const float*)d_in[1];
    const float* Wqi = (const float*)d_in[2];  const float* bqi = (const float*)d_in[3];
    const float* Wkt = (const float*)d_in[4];  const float* bkt = (const float*)d_in[5];
    const float* Wvt = (const float*)d_in[6];  const float* bvt = (const float*)d_in[7];
    const float* Wqt = (const float*)d_in[8];  const float* bqt = (const float*)d_in[9];
    const float* Wki = (const float*)d_in[10]; const float* bki = (const float*)d_in[11];
    const float* Wvi = (const float*)d_in[12]; const float* bvi = (const float*)d_in[13];
    const float* Wo  = (const float*)d_in[14]; const float* bo  = (const float*)d_in[15];
    float* out = (float*)d_out;

    cudaFuncSetAttribute(hgemm3<0,0,3>, cudaFuncAttributeMaxDynamicSharedMemorySize, GSMEM);
    cudaFuncSetAttribute(hgemm3<0,1,1>, cudaFuncAttributeMaxDynamicSharedMemorySize, GSMEM);
    cudaFuncSetAttribute(hgemm3<1,0,1>, cudaFuncAttributeMaxDynamicSharedMemorySize, GSMEM);
    cudaFuncSetAttribute(hgemm3<1,1,3>, cudaFuncAttributeMaxDynamicSharedMemorySize, GSMEM);
    cudaFuncSetAttribute(hgemm3<1,2,1>, cudaFuncAttributeMaxDynamicSharedMemorySize, GSMEM);

    float *S;
    __half *img2, *tab2, *w2, *wo2, *qk2, *vt2, *S2, *fused2;
    cudaGetSymbolAddress((void**)&S,      g_S);
    cudaGetSymbolAddress((void**)&img2,   g_img2);
    cudaGetSymbolAddress((void**)&tab2,   g_tab2);
    cudaGetSymbolAddress((void**)&w2,     g_w2);
    cudaGetSymbolAddress((void**)&wo2,    g_wo2);
    cudaGetSymbolAddress((void**)&qk2,    g_qk2);
    cudaGetSymbolAddress((void**)&vt2,    g_vt2);
    cudaGetSymbolAddress((void**)&S2,     g_S2);
    cudaGetSymbolAddress((void**)&fused2, g_fused2);

    const size_t W2SZ = (size_t)DC * 2 * DC;
    __half* wqi2 = w2 + 0 * W2SZ;  __half* wkt2 = w2 + 1 * W2SZ;
    __half* wvt2 = w2 + 2 * W2SZ;  __half* wqt2 = w2 + 3 * W2SZ;
    __half* wki2 = w2 + 4 * W2SZ;  __half* wvi2 = w2 + 5 * W2SZ;
    const size_t QK2 = (size_t)NR * 2 * DC;
    __half* q12 = qk2 + 0 * QK2;   __half* k12 = qk2 + 1 * QK2;
    __half* q22 = qk2 + 2 * QK2;   __half* k22 = qk2 + 3 * QK2;
    __half* v1t2 = vt2;            __half* v2t2 = vt2 + (size_t)DC * 2 * NR;

    // ---- launches 0-2: input conversions + combined weight prep ----
    const size_t tot = (size_t)NR * DC;
    convert_split<<<(unsigned)((tot / 4 + 255) / 256), 256>>>(img, img2, DC, tot);
    convert_split<<<(unsigned)((tot / 4 + 255) / 256), 256>>>(tab, tab2, DC, tot);
    weight_prep<<<dim3(64, 64, 7), dim3(32, 8)>>>(
        Wqi, Wkt, Wvt, Wqt, Wki, Wvi, Wo,
        wqi2, wkt2, wvt2, wqt2, wki2, wvi2, wo2);

    // ---- launches 3-6: Q/K projections (3-pass, accuracy-critical) ----
    dim3 gP(DC / 128, NR / 128);
    hgemm3<1,1,3><<<gP, TPB, GSMEM>>>(img2, wqi2, DC, 2*DC, 2*DC, nullptr, q12, 2*DC, DC, bqi);
    hgemm3<1,1,3><<<gP, TPB, GSMEM>>>(tab2, wkt2, DC, 2*DC, 2*DC, nullptr, k12, 2*DC, DC, bkt);
    hgemm3<1,1,3><<<gP, TPB, GSMEM>>>(tab2, wqt2, DC, 2*DC, 2*DC, nullptr, q22, 2*DC, DC, bqt);
    hgemm3<1,1,3><<<gP, TPB, GSMEM>>>(img2, wki2, DC, 2*DC, 2*DC, nullptr, k22, 2*DC, DC, bki);
    // ---- V projections (1-pass: only V-hi is ever consumed by PV) ----
    dim3 gV(NR / 128, DC / 128);
    hgemm3<1,2,1><<<gV, TPB, GSMEM>>>(wvt2, tab2, DC, 2*DC, 2*DC, nullptr, v1t2, 2*NR, NR, bvt);
    hgemm3<1,2,1><<<gV, TPB, GSMEM>>>(wvi2, img2, DC, 2*DC, 2*DC, nullptr, v2t2, 2*NR, NR, bvi);

    dim3 gS(NR / 128, NR / 128);
    dim3 gPV(DC / 128, NR / 128);

    // ---- branch 1: attended_tabular -> fused cols [1024,2048) ----
    hgemm3<0,0,3><<<gS, TPB, GSMEM>>>(q12, k12, DC, 2*DC, 2*DC, S, nullptr, NR, 0, nullptr);
    softmax_hi<<<NR, 256>>>(S, S2);
    hgemm3<1,0,1><<<gPV, TPB, GSMEM>>>(S2, v1t2, NR, NR, 2*NR, nullptr, fused2 + DC, 4*DC, 2*DC, nullptr);

    // ---- branch 2: attended_image -> fused cols [0,1024) ----
    hgemm3<0,0,3><<<gS, TPB, GSMEM>>>(q22, k22, DC, 2*DC, 2*DC, S, nullptr, NR, 0, nullptr);
    softmax_hi<<<NR, 256>>>(S, S2);
    hgemm3<1,0,1><<<gPV, TPB, GSMEM>>>(S2, v2t2, NR, NR, 2*NR, nullptr, fused2, 4*DC, 2*DC, nullptr);

    // ---- output projection (fp32 out, 1-pass) ----
    dim3 gO(2 * DC / 128, NR / 128);
    hgemm3<0,1,1><<<gO, TPB, GSMEM>>>(fused2, wo2, 2*DC, 4*DC, 4*DC, out, nullptr, 2*DC, 0, bo);
}

// round 9
// speedup vs baseline: 1.2013x; 1.0613x over previous
#include <cuda_runtime.h>
#include <cuda_fp16.h>
#include <cstdint>

#define NR 8192
#define DC 1024

// ---------------------------------------------------------------------------
// Static device scratch. Split-fp16 tensors stored [rows, 2K]: hi | lo.
// ---------------------------------------------------------------------------
__device__ float  g_S[(size_t)2 * NR * NR];             // 512 MB logits (branch 0/1)
__device__ __half g_img2[(size_t)NR * 2 * DC];
__device__ __half g_tab2[(size_t)NR * 2 * DC];
__device__ __half g_w2[(size_t)6 * DC * 2 * DC];        // 6x W^T [1024,2048]
__device__ __half g_wo2[(size_t)2 * DC * 4 * DC];       // Wo^T [2048,4096]
__device__ __half g_qk2[(size_t)4 * NR * 2 * DC];       // q1,k1,q2,k2
__device__ __half g_vt2[(size_t)2 * DC * 2 * NR];       // v1^T,v2^T [1024,16384]
__device__ __half g_S2[(size_t)2 * NR * NR];            // probs hi-only, 2 branches
__device__ __half g_fused2[(size_t)NR * 4 * DC];        // fused split [8192,4096]

// ---------------------------------------------------------------------------
// helpers
// ---------------------------------------------------------------------------
__device__ __forceinline__ uint32_t smem_u32(const void* p) {
    uint32_t a;
    asm("{ .reg .u64 t; cvta.to.shared.u64 t, %1; cvt.u32.u64 %0, t; }" : "=r"(a) : "l"(p));
    return a;
}
__device__ __forceinline__ void cp16(uint32_t d, const void* g) {
    asm volatile("cp.async.cg.shared.global [%0], [%1], 16;"
                 :: "r"(d), "l"(__cvta_generic_to_global(g)) : "memory");
}
__device__ __forceinline__ void ldm4(uint32_t* r, uint32_t a) {
    asm volatile("ldmatrix.sync.aligned.m8n8.x4.shared.b16 {%0,%1,%2,%3}, [%4];"
                 : "=r"(r[0]), "=r"(r[1]), "=r"(r[2]), "=r"(r[3]) : "r"(a));
}
__device__ __forceinline__ void mma16816(float* d, const uint32_t* a, const uint32_t* b) {
    asm("mma.sync.aligned.m16n8k16.row.col.f32.f16.f16.f32 "
        "{%0,%1,%2,%3}, {%4,%5,%6,%7}, {%8,%9}, {%0,%1,%2,%3};"
        : "+f"(d[0]), "+f"(d[1]), "+f"(d[2]), "+f"(d[3])
        : "r"(a[0]), "r"(a[1]), "r"(a[2]), "r"(a[3]), "r"(b[0]), "r"(b[1]));
}
__device__ __forceinline__ void mma16816h(uint32_t* d, const uint32_t* a, const uint32_t* b) {
    asm("mma.sync.aligned.m16n8k16.row.col.f16.f16.f16.f16 "
        "{%0,%1}, {%2,%3,%4,%5}, {%6,%7}, {%0,%1};"
        : "+r"(d[0]), "+r"(d[1])
        : "r"(a[0]), "r"(a[1]), "r"(a[2]), "r"(a[3]), "r"(b[0]), "r"(b[1]));
}
__device__ __forceinline__ __half2 split_hi(float x0, float x1, __half2& lo) {
    __half h0 = __float2half_rn(x0), h1 = __float2half_rn(x1);
    lo = __halves2half2(__float2half_rn(x0 - __half2float(h0)),
                        __float2half_rn(x1 - __half2float(h1)));
    return __halves2half2(h0, h1);
}

// ---------------------------------------------------------------------------
// Batched split-fp16 NT GEMM:  C[M,N] = A[M,K] . B[N,K]^T per blockIdx.z
// PASSES=3: corrections (Ahi·Blo, Alo·Bhi) accumulated in FP16, then hi·hi
//           pass in FP32.  PASSES=1: hi·hi only (FP32).
// Tile 128x128xBK64, 256 threads (8 warps 2x4, each 64x32 register tile),
// cp.async 3-stage, ldmatrix fragment loads.
// OUT_MODE: 0 = fp32 to Cf, 1 = split fp16 to Ch (hi at col, lo at col+lo_off)
// BIAS: 0 none, 1 per-column, 2 per-row
// ---------------------------------------------------------------------------
#define TPB 256
#define AST 144                       // 128B data + 16B pad (36 banks/row)
#define STG (128 * AST * 2)           // 36864 B per stage (A+B)
#define GSMEM (3 * STG)               // 110592 B

struct GB { const __half* A; const __half* B; const float* bias; float* Cf; __half* Ch; };
struct GB4 { GB g[4]; };

template <int OUT_MODE, int BIAS, int PASSES>
__global__ __launch_bounds__(TPB, 2)
void hgemm3(const __grid_constant__ GB4 batch, int K,
            size_t ldA, size_t ldB, int ldc, int lo_off)
{
    extern __shared__ char smc[];
    const uint32_t sb = smem_u32(smc);
    const GB gb = batch.g[blockIdx.z];
    const __half* __restrict__ A = gb.A;
    const __half* __restrict__ B = gb.B;
    const int tid = threadIdx.x;
    const int wid = tid >> 5, lane = tid & 31;
    const int g = lane >> 2, t = lane & 3;
    const int wm = wid & 1, wn = wid >> 1;          // 2x4 warp grid, 64x32 each
    const int m0 = blockIdx.y * 128, n0 = blockIdx.x * 128;

    const int K64 = K >> 6;
    const int corr  = (PASSES == 3) ? 2 * K64 : 0;
    const int total = corr + K64;

    const int lr = tid >> 3;              // 0..31 (row base, step 32)
    const int lc  = (tid & 7) * 8;        // half offset within 64-col row
    const int lcB = (tid & 7) * 16;       // byte offset

    auto load_stage = [&](int s, int step) {
        if (step < total) {
            const int seg = step / K64, kk = step - seg * K64;
            // seg0: hi·lo, seg1: lo·hi, seg2 (or PASSES==1 seg0): hi·hi
            const size_t ak = (size_t)kk * 64 +
                              ((PASSES == 3 && seg == 1) ? (size_t)K : 0);
            const size_t bk = (size_t)kk * 64 +
                              ((PASSES == 3 && seg == 0) ? (size_t)K : 0);
            const __half* ga = A + (size_t)(m0 + lr) * ldA + ak + lc;
            const __half* gbp = B + (size_t)(n0 + lr) * ldB + bk + lc;
            const uint32_t da = sb + s * STG + lr * AST + lcB;
            const uint32_t db = da + 128 * AST;
#pragma unroll
            for (int i = 0; i < 4; ++i) {
                cp16(da + i * 32 * AST, ga + (size_t)i * 32 * ldA);
                cp16(db + i * 32 * AST, gbp + (size_t)i * 32 * ldB);
            }
        }
        asm volatile("cp.async.commit_group;" ::: "memory");
    };

    // ldmatrix per-lane offsets within a stage
    const uint32_t aoff = (uint32_t)(wm * 64 + (lane & 15)) * AST + ((lane >> 4) << 4);
    const uint32_t boff = 128 * AST +
        (uint32_t)(wn * 32 + ((lane & 7) | ((lane >> 1) & 8))) * AST +
        (((lane >> 3) & 1) << 4);

    load_stage(0, 0);
    load_stage(1, 1);

    // ---- phase 1: correction passes, fp16 accumulate ----
    uint32_t acc16[4][4][2];
#pragma unroll
    for (int i = 0; i < 4; ++i)
#pragma unroll
        for (int j = 0; j < 4; ++j) { acc16[i][j][0] = 0u; acc16[i][j][1] = 0u; }

    for (int step = 0; step < corr; ++step) {
        asm volatile("cp.async.wait_group 1;" ::: "memory");
        __syncthreads();
        load_stage((step + 2) % 3, step + 2);
        const uint32_t sbase = sb + (step % 3) * STG;
#pragma unroll
        for (int kh = 0; kh < 4; ++kh) {
            const uint32_t ko = kh * 32;
            uint32_t af[4][4], bf[4][2];
#pragma unroll
            for (int mt = 0; mt < 4; ++mt)
                ldm4(af[mt], sbase + aoff + (uint32_t)mt * 16 * AST + ko);
#pragma unroll
            for (int np = 0; np < 2; ++np) {
                uint32_t r[4];
                ldm4(r, sbase + boff + (uint32_t)np * 16 * AST + ko);
                bf[np * 2][0] = r[0];      bf[np * 2][1] = r[1];
                bf[np * 2 + 1][0] = r[2];  bf[np * 2 + 1][1] = r[3];
            }
#pragma unroll
            for (int mt = 0; mt < 4; ++mt)
#pragma unroll
                for (int nt = 0; nt < 4; ++nt)
                    mma16816h(acc16[mt][nt], af[mt], bf[nt]);
        }
    }

    // ---- convert correction accumulators to fp32 ----
    float acc[4][4][4];
#pragma unroll
    for (int i = 0; i < 4; ++i)
#pragma unroll
        for (int j = 0; j < 4; ++j) {
            const __half2 h0 = *reinterpret_cast<const __half2*>(&acc16[i][j][0]);
            const __half2 h1 = *reinterpret_cast<const __half2*>(&acc16[i][j][1]);
            acc[i][j][0] = __low2float(h0);  acc[i][j][1] = __high2float(h0);
            acc[i][j][2] = __low2float(h1);  acc[i][j][3] = __high2float(h1);
        }

    // ---- phase 2: hi·hi pass, fp32 accumulate ----
    for (int step = corr; step < total; ++step) {
        asm volatile("cp.async.wait_group 1;" ::: "memory");
        __syncthreads();
        load_stage((step + 2) % 3, step + 2);
        const uint32_t sbase = sb + (step % 3) * STG;
#pragma unroll
        for (int kh = 0; kh < 4; ++kh) {
            const uint32_t ko = kh * 32;
            uint32_t af[4][4], bf[4][2];
#pragma unroll
            for (int mt = 0; mt < 4; ++mt)
                ldm4(af[mt], sbase + aoff + (uint32_t)mt * 16 * AST + ko);
#pragma unroll
            for (int np = 0; np < 2; ++np) {
                uint32_t r[4];
                ldm4(r, sbase + boff + (uint32_t)np * 16 * AST + ko);
                bf[np * 2][0] = r[0];      bf[np * 2][1] = r[1];
                bf[np * 2 + 1][0] = r[2];  bf[np * 2 + 1][1] = r[3];
            }
#pragma unroll
            for (int mt = 0; mt < 4; ++mt)
#pragma unroll
                for (int nt = 0; nt < 4; ++nt)
                    mma16816(acc[mt][nt], af[mt], bf[nt]);
        }
    }

    // ---- epilogue ----
#pragma unroll
    for (int mt = 0; mt < 4; ++mt) {
        const int r0 = m0 + wm * 64 + mt * 16 + g;
        const int r1 = r0 + 8;
#pragma unroll
        for (int nt = 0; nt < 4; ++nt) {
            const int col = n0 + wn * 32 + nt * 8 + 2 * t;
            float v00 = acc[mt][nt][0], v01 = acc[mt][nt][1];
            float v10 = acc[mt][nt][2], v11 = acc[mt][nt][3];
            if (BIAS == 1) {
                const float b0 = gb.bias[col], b1 = gb.bias[col + 1];
                v00 += b0; v01 += b1; v10 += b0; v11 += b1;
            } else if (BIAS == 2) {
                const float b0 = gb.bias[r0], b1 = gb.bias[r1];
                v00 += b0; v01 += b0; v10 += b1; v11 += b1;
            }
            if (OUT_MODE == 0) {
                *reinterpret_cast<float2*>(&gb.Cf[(size_t)r0 * ldc + col]) = make_float2(v00, v01);
                *reinterpret_cast<float2*>(&gb.Cf[(size_t)r1 * ldc + col]) = make_float2(v10, v11);
            } else {
                __half2 lo0, lo1;
                __half2 hi0 = split_hi(v00, v01, lo0);
                __half2 hi1 = split_hi(v10, v11, lo1);
                __half2* p0 = reinterpret_cast<__half2*>(&gb.Ch[(size_t)r0 * ldc + col]);
                __half2* p1 = reinterpret_cast<__half2*>(&gb.Ch[(size_t)r1 * ldc + col]);
                p0[0] = hi0;  p0[lo_off / 2] = lo0;
                p1[0] = hi1;  p1[lo_off / 2] = lo1;
            }
        }
    }
}

// ---------------------------------------------------------------------------
// fp32 [R,C] -> split fp16 [R,2C]
// ---------------------------------------------------------------------------
__global__ __launch_bounds__(256)
void convert_split(const float* __restrict__ in, __half* __restrict__ out,
                   int C, size_t total)
{
    size_t i = ((size_t)blockIdx.x * 256 + threadIdx.x) * 4;
    if (i >= total) return;
    float4 v = *reinterpret_cast<const float4*>(&in[i]);
    size_t r = i / C;
    int c = (int)(i - r * C);
    __half2 lo0, lo1;
    __half2 hi0 = split_hi(v.x, v.y, lo0);
    __half2 hi1 = split_hi(v.z, v.w, lo1);
    __half* row = out + r * (2 * (size_t)C);
    *reinterpret_cast<__half2*>(&row[c])         = hi0;
    *reinterpret_cast<__half2*>(&row[c + 2])     = hi1;
    *reinterpret_cast<__half2*>(&row[C + c])     = lo0;
    *reinterpret_cast<__half2*>(&row[C + c + 2]) = lo1;
}

// ---------------------------------------------------------------------------
// All 7 weight transposes in ONE launch: in[R,C] -> split fp16 out[C,2R].
// ---------------------------------------------------------------------------
__global__ __launch_bounds__(256)
void weight_prep(const float* w0, const float* w1, const float* w2c,
                 const float* w3, const float* w4, const float* w5,
                 const float* w6,
                 __half* o0, __half* o1, __half* o2, __half* o3,
                 __half* o4, __half* o5, __half* o6)
{
    const float* src; __half* dst; int R, C;
    switch (blockIdx.z) {
        case 0: src = w0; dst = o0; R = DC; C = DC; break;
        case 1: src = w1; dst = o1; R = DC; C = DC; break;
        case 2: src = w2c; dst = o2; R = DC; C = DC; break;
        case 3: src = w3; dst = o3; R = DC; C = DC; break;
        case 4: src = w4; dst = o4; R = DC; C = DC; break;
        case 5: src = w5; dst = o5; R = DC; C = DC; break;
        default: src = w6; dst = o6; R = 2 * DC; C = 2 * DC; break;
    }
    const int bx = blockIdx.x * 32, by = blockIdx.y * 32;
    if (bx >= C || by >= R) return;

    __shared__ float tl[32][33];
    const int tx = threadIdx.x, ty = threadIdx.y;
#pragma unroll
    for (int j = ty; j < 32; j += 8)
        tl[j][tx] = src[(size_t)(by + j) * C + bx + tx];
    __syncthreads();
#pragma unroll
    for (int j = ty; j < 32; j += 8) {
        const float v = tl[tx][j];
        const __half h = __float2half_rn(v);
        const __half l = __float2half_rn(v - __half2float(h));
        __half* row = dst + (size_t)(bx + j) * (2 * (size_t)R);
        row[by + tx]     = h;
        row[R + by + tx] = l;
    }
}

// ---------------------------------------------------------------------------
// Row softmax (batched over blockIdx.y = branch): fp32 logits -> fp16 probs
// ---------------------------------------------------------------------------
__global__ __launch_bounds__(256)
void softmax_hi(const float* __restrict__ S, __half* __restrict__ S2)
{
    __shared__ float row[NR];
    __shared__ float red[256];
    const size_t off = (size_t)blockIdx.y * NR * NR + (size_t)blockIdx.x * NR;
    const float* p = S + off;
    __half* o = S2 + off;
    const int tid = threadIdx.x;

    float lmax = -3.0e38f;
    for (int i = tid * 4; i < NR; i += 1024) {
        float4 v = *reinterpret_cast<const float4*>(&p[i]);
        *reinterpret_cast<float4*>(&row[i]) = v;
        lmax = fmaxf(lmax, fmaxf(fmaxf(v.x, v.y), fmaxf(v.z, v.w)));
    }
    red[tid] = lmax;
    __syncthreads();
#pragma unroll
    for (int s = 128; s > 0; s >>= 1) {
        if (tid < s) red[tid] = fmaxf(red[tid], red[tid + s]);
        __syncthreads();
    }
    const float bmax = red[0];
    __syncthreads();

    float lsum = 0.0f;
    for (int i = tid * 4; i < NR; i += 1024) {
        float4 v = *reinterpret_cast<float4*>(&row[i]);
        v.x = __expf(v.x - bmax); v.y = __expf(v.y - bmax);
        v.z = __expf(v.z - bmax); v.w = __expf(v.w - bmax);
        lsum += v.x + v.y + v.z + v.w;
        *reinterpret_cast<float4*>(&row[i]) = v;
    }
    red[tid] = lsum;
    __syncthreads();
#pragma unroll
    for (int s = 128; s > 0; s >>= 1) {
        if (tid < s) red[tid] += red[tid + s];
        __syncthreads();
    }
    const float inv = 1.0f / red[0];
    __syncthreads();

    for (int i = tid * 4; i < NR; i += 1024) {
        float4 v = *reinterpret_cast<float4*>(&row[i]);
        *reinterpret_cast<__half2*>(&o[i]) =
            __halves2half2(__float2half_rn(v.x * inv), __float2half_rn(v.y * inv));
        *reinterpret_cast<__half2*>(&o[i + 2]) =
            __halves2half2(__float2half_rn(v.z * inv), __float2half_rn(v.w * inv));
    }
}

// ---------------------------------------------------------------------------
// Launch sequence
// ---------------------------------------------------------------------------
extern "C" void kernel_launch(void* const* d_in, const int* in_sizes, int n_in,
                              void* d_out, int out_size)
{
    const float* img = (const float*)d_in[0];
    const float* tab = (const float*)d_in[1];
    const float* Wqi = (const float*)d_in[2];  const float* bqi = (const float*)d_in[3];
    const float* Wkt = (const float*)d_in[4];  const float* bkt = (const float*)d_in[5];
    const float* Wvt = (const float*)d_in[6];  const float* bvt = (const float*)d_in[7];
    const float* Wqt = (const float*)d_in[8];  const float* bqt = (const float*)d_in[9];
    const float* Wki = (const float*)d_in[10]; const float* bki = (const float*)d_in[11];
    const float* Wvi = (const float*)d_in[12]; const float* bvi = (const float*)d_in[13];
    const float* Wo  = (const float*)d_in[14]; const float* bo  = (const float*)d_in[15];
    float* out = (float*)d_out;

    cudaFuncSetAttribute(hgemm3<0,0,3>, cudaFuncAttributeMaxDynamicSharedMemorySize, GSMEM);
    cudaFuncSetAttribute(hgemm3<0,1,1>, cudaFuncAttributeMaxDynamicSharedMemorySize, GSMEM);
    cudaFuncSetAttribute(hgemm3<1,0,1>, cudaFuncAttributeMaxDynamicSharedMemorySize, GSMEM);
    cudaFuncSetAttribute(hgemm3<1,1,3>, cudaFuncAttributeMaxDynamicSharedMemorySize, GSMEM);
    cudaFuncSetAttribute(hgemm3<1,2,1>, cudaFuncAttributeMaxDynamicSharedMemorySize, GSMEM);

    float *S;
    __half *img2, *tab2, *w2, *wo2, *qk2, *vt2, *S2, *fused2;
    cudaGetSymbolAddress((void**)&S,      g_S);
    cudaGetSymbolAddress((void**)&img2,   g_img2);
    cudaGetSymbolAddress((void**)&tab2,   g_tab2);
    cudaGetSymbolAddress((void**)&w2,     g_w2);
    cudaGetSymbolAddress((void**)&wo2,    g_wo2);
    cudaGetSymbolAddress((void**)&qk2,    g_qk2);
    cudaGetSymbolAddress((void**)&vt2,    g_vt2);
    cudaGetSymbolAddress((void**)&S2,     g_S2);
    cudaGetSymbolAddress((void**)&fused2, g_fused2);

    const size_t W2SZ = (size_t)DC * 2 * DC;
    __half* wqi2 = w2 + 0 * W2SZ;  __half* wkt2 = w2 + 1 * W2SZ;
    __half* wvt2 = w2 + 2 * W2SZ;  __half* wqt2 = w2 + 3 * W2SZ;
    __half* wki2 = w2 + 4 * W2SZ;  __half* wvi2 = w2 + 5 * W2SZ;
    const size_t QK2 = (size_t)NR * 2 * DC;
    __half* q12 = qk2 + 0 * QK2;   __half* k12 = qk2 + 1 * QK2;
    __half* q22 = qk2 + 2 * QK2;   __half* k22 = qk2 + 3 * QK2;
    __half* v1t2 = vt2;            __half* v2t2 = vt2 + (size_t)DC * 2 * NR;
    float*  S_1 = S;               float*  S_2 = S + (size_t)NR * NR;
    __half* P_1 = S2;              __half* P_2 = S2 + (size_t)NR * NR;

    // ---- launches 0-2: input conversions + combined weight prep ----
    const size_t tot = (size_t)NR * DC;
    convert_split<<<(unsigned)((tot / 4 + 255) / 256), 256>>>(img, img2, DC, tot);
    convert_split<<<(unsigned)((tot / 4 + 255) / 256), 256>>>(tab, tab2, DC, tot);
    weight_prep<<<dim3(64, 64, 7), dim3(32, 8)>>>(
        Wqi, Wkt, Wvt, Wqt, Wki, Wvi, Wo,
        wqi2, wkt2, wvt2, wqt2, wki2, wvi2, wo2);

    // ---- launch 3: all 4 Q/K projections (3-pass, f16-acc corrections) ----
    {
        GB4 b = {{ { img2, wqi2, bqi, nullptr, q12 },
                   { tab2, wkt2, bkt, nullptr, k12 },
                   { tab2, wqt2, bqt, nullptr, q22 },
                   { img2, wki2, bki, nullptr, k22 } }};
        hgemm3<1,1,3><<<dim3(DC/128, NR/128, 4), TPB, GSMEM>>>(b, DC, 2*DC, 2*DC, 2*DC, DC);
    }
    // ---- launch 4: both V^T projections (1-pass) ----
    {
        GB4 b = {{ { wvt2, tab2, bvt, nullptr, v1t2 },
                   { wvi2, img2, bvi, nullptr, v2t2 },
                   {}, {} }};
        hgemm3<1,2,1><<<dim3(NR/128, DC/128, 2), TPB, GSMEM>>>(b, DC, 2*DC, 2*DC, 2*NR, NR);
    }
    // ---- launch 5: both QK^T (3-pass, f16-acc corrections) — ncu target ----
    {
        GB4 b = {{ { q12, k12, nullptr, S_1, nullptr },
                   { q22, k22, nullptr, S_2, nullptr },
                   {}, {} }};
        hgemm3<0,0,3><<<dim3(NR/128, NR/128, 2), TPB, GSMEM>>>(b, DC, 2*DC, 2*DC, NR, 0);
    }
    // ---- launch 6: both softmaxes ----
    softmax_hi<<<dim3(NR, 2), 256>>>(S, S2);
    // ---- launch 7: both P·V (1-pass) ----
    {
        GB4 b = {{ { P_1, v1t2, nullptr, nullptr, fused2 + DC },
                   { P_2, v2t2, nullptr, nullptr, fused2 },
                   {}, {} }};
        hgemm3<1,0,1><<<dim3(DC/128, NR/128, 2), TPB, GSMEM>>>(b, NR, NR, 2*NR, 4*DC, 2*DC);
    }
    // ---- launch 8: output projection (1-pass, fp32 out) ----
    {
        GB4 b = {{ { fused2, wo2, bo, out, nullptr }, {}, {}, {} }};
        hgemm3<0,1,1><<<dim3(2*DC/128, NR/128, 1), TPB, GSMEM>>>(b, 2*DC, 4*DC, 4*DC, 2*DC, 0);
    }
}

// round 10
// speedup vs baseline: 1.4949x; 1.2444x over previous
#include <cuda_runtime.h>
#include <cuda_fp16.h>
#include <cstdint>

#define NR 8192
#define DC 1024

// int8 quantization scales: value = int8 / S;  hi: 1/32 (range ±4), lo: 1/65536
#define S8_HI 32.0f
#define S8_LO 65536.0f
#define S_COMB (1.0f / 2097152.0f)   // (1/32)*(1/65536), equal for both sweeps

// ---------------------------------------------------------------------------
// Static device scratch. Split-fp16 tensors stored [rows, 2K]: hi | lo.
// ---------------------------------------------------------------------------
__device__ float  g_S[(size_t)2 * NR * NR];             // logits (branch 0/1)
__device__ __half g_img2[(size_t)NR * 2 * DC];
__device__ __half g_tab2[(size_t)NR * 2 * DC];
__device__ __half g_w2[(size_t)6 * DC * 2 * DC];        // 6x W^T [1024,2048]
__device__ __half g_wo2[(size_t)2 * DC * 4 * DC];       // Wo^T [2048,4096]
__device__ __half g_qk2[(size_t)4 * NR * 2 * DC];       // q1,k1,q2,k2 fp16 hi|lo
__device__ int8_t g_qk8[(size_t)4 * NR * 2 * DC];       // q1,k1,q2,k2 int8 hi|lo
__device__ __half g_vt2[(size_t)2 * DC * 2 * NR];       // v1^T,v2^T
__device__ __half g_S2[(size_t)2 * NR * NR];            // probs hi-only, 2 branches
__device__ __half g_fused2[(size_t)NR * 4 * DC];        // fused split [8192,4096]

// ---------------------------------------------------------------------------
// helpers
// ---------------------------------------------------------------------------
__device__ __forceinline__ uint32_t smem_u32(const void* p) {
    uint32_t a;
    asm("{ .reg .u64 t; cvta.to.shared.u64 t, %1; cvt.u32.u64 %0, t; }" : "=r"(a) : "l"(p));
    return a;
}
__device__ __forceinline__ void cp16(uint32_t d, const void* g) {
    asm volatile("cp.async.cg.shared.global [%0], [%1], 16;"
                 :: "r"(d), "l"(__cvta_generic_to_global(g)) : "memory");
}
__device__ __forceinline__ void ldm4(uint32_t* r, uint32_t a) {
    asm volatile("ldmatrix.sync.aligned.m8n8.x4.shared.b16 {%0,%1,%2,%3}, [%4];"
                 : "=r"(r[0]), "=r"(r[1]), "=r"(r[2]), "=r"(r[3]) : "r"(a));
}
__device__ __forceinline__ void mma16816(float* d, const uint32_t* a, const uint32_t* b) {
    asm("mma.sync.aligned.m16n8k16.row.col.f32.f16.f16.f32 "
        "{%0,%1,%2,%3}, {%4,%5,%6,%7}, {%8,%9}, {%0,%1,%2,%3};"
        : "+f"(d[0]), "+f"(d[1]), "+f"(d[2]), "+f"(d[3])
        : "r"(a[0]), "r"(a[1]), "r"(a[2]), "r"(a[3]), "r"(b[0]), "r"(b[1]));
}
__device__ __forceinline__ void mma16816h(uint32_t* d, const uint32_t* a, const uint32_t* b) {
    asm("mma.sync.aligned.m16n8k16.row.col.f16.f16.f16.f16 "
        "{%0,%1}, {%2,%3,%4,%5}, {%6,%7}, {%0,%1};"
        : "+r"(d[0]), "+r"(d[1])
        : "r"(a[0]), "r"(a[1]), "r"(a[2]), "r"(a[3]), "r"(b[0]), "r"(b[1]));
}
__device__ __forceinline__ void mma16832s8(int* d, const uint32_t* a, const uint32_t* b) {
    asm("mma.sync.aligned.m16n8k32.row.col.s32.s8.s8.s32 "
        "{%0,%1,%2,%3}, {%4,%5,%6,%7}, {%8,%9}, {%0,%1,%2,%3};"
        : "+r"(d[0]), "+r"(d[1]), "+r"(d[2]), "+r"(d[3])
        : "r"(a[0]), "r"(a[1]), "r"(a[2]), "r"(a[3]), "r"(b[0]), "r"(b[1]));
}
__device__ __forceinline__ __half2 split_hi(float x0, float x1, __half2& lo) {
    __half h0 = __float2half_rn(x0), h1 = __float2half_rn(x1);
    lo = __halves2half2(__float2half_rn(x0 - __half2float(h0)),
                        __float2half_rn(x1 - __half2float(h1)));
    return __halves2half2(h0, h1);
}
__device__ __forceinline__ int8_t q8clamp(float x, float s) {
    int v = __float2int_rn(x * s);
    v = v > 127 ? 127 : (v < -127 ? -127 : v);
    return (int8_t)v;
}

// ---------------------------------------------------------------------------
// Batched split NT GEMM:  C[M,N] = A[M,K] . B[N,K]^T per blockIdx.z
// PASSES=3: fp16-acc corrections (Ahi·Blo, Alo·Bhi) + fp32 hi·hi pass.
// PASSES=4: INT8 corrections (2 sweeps, shared s32 acc, k=128/step) + fp32 hi·hi.
// PASSES=1: hi·hi only.
// Tile 128x128, 256 threads (8 warps 2x4, 64x32 each), cp.async 3-stage.
// OUT_MODE: 0 = fp32 to Cf, 1 = split fp16 to Ch.  EMIT8: also emit int8 hi|lo.
// BIAS: 0 none, 1 per-column, 2 per-row
// ---------------------------------------------------------------------------
#define TPB 256
#define AST 144                       // 128B data + 16B pad (36 banks/row)
#define STG (128 * AST * 2)           // 36864 B per stage (A+B)
#define GSMEM (3 * STG)               // 110592 B

struct GB { const __half* A; const __half* B; const int8_t* A8; const int8_t* B8;
            const float* bias; float* Cf; __half* Ch; int8_t* C8; };
struct GB4 { GB g[4]; };

template <int OUT_MODE, int BIAS, int PASSES, int EMIT8>
__global__ __launch_bounds__(TPB, 2)
void hgemm3(const __grid_constant__ GB4 batch, int K,
            size_t ldA, size_t ldB, size_t ld8, int ldc, int lo_off)
{
    extern __shared__ char smc[];
    const uint32_t sb = smem_u32(smc);
    const GB gb = batch.g[blockIdx.z];
    const int tid = threadIdx.x;
    const int wid = tid >> 5, lane = tid & 31;
    const int g = lane >> 2, t = lane & 3;
    const int wm = wid & 1, wn = wid >> 1;          // 2x4 warp grid, 64x32 each
    const int m0 = blockIdx.y * 128, n0 = blockIdx.x * 128;

    const int K64 = K >> 6;
    const int corr  = (PASSES == 3) ? 2 * K64 : (PASSES == 4) ? K64 : 0;
    const int total = corr + K64;

    const int lr = tid >> 3;              // 0..31 (row base, step 32)
    const int lc  = (tid & 7) * 8;        // half offset within 64-col fp16 row
    const int lcB = (tid & 7) * 16;       // byte offset

    auto load_stage = [&](int s, int step) {
        if (step < total) {
            const uint32_t da = sb + s * STG + lr * AST + lcB;
            const uint32_t db = da + 128 * AST;
            if (PASSES == 4 && step < corr) {
                // int8 sweeps: each step covers k=128 (128 bytes/row)
                const int spw = K >> 7;              // steps per sweep
                const int swp = step / spw, kk = step - swp * spw;
                const int a8o = swp ? K : 0;         // sweep0: Ahi·Blo, sweep1: Alo·Bhi
                const int b8o = swp ? 0 : K;
                const int8_t* ga  = gb.A8 + (size_t)(m0 + lr) * ld8 + a8o + kk * 128 + lcB;
                const int8_t* gbp = gb.B8 + (size_t)(n0 + lr) * ld8 + b8o + kk * 128 + lcB;
#pragma unroll
                for (int i = 0; i < 4; ++i) {
                    cp16(da + i * 32 * AST, ga  + (size_t)i * 32 * ld8);
                    cp16(db + i * 32 * AST, gbp + (size_t)i * 32 * ld8);
                }
            } else {
                int seg, kk;
                if (PASSES == 3) { seg = step / K64; kk = step - seg * K64; }
                else             { seg = 2;          kk = step - corr; }
                const size_t ak = (size_t)kk * 64 + ((PASSES == 3 && seg == 1) ? (size_t)K : 0);
                const size_t bk = (size_t)kk * 64 + ((PASSES == 3 && seg == 0) ? (size_t)K : 0);
                const __half* ga  = gb.A + (size_t)(m0 + lr) * ldA + ak + lc;
                const __half* gbp = gb.B + (size_t)(n0 + lr) * ldB + bk + lc;
#pragma unroll
                for (int i = 0; i < 4; ++i) {
                    cp16(da + i * 32 * AST, ga  + (size_t)i * 32 * ldA);
                    cp16(db + i * 32 * AST, gbp + (size_t)i * 32 * ldB);
                }
            }
        }
        asm volatile("cp.async.commit_group;" ::: "memory");
    };

    // ldmatrix per-lane offsets within a stage (identical for fp16 and int8)
    const uint32_t aoff = (uint32_t)(wm * 64 + (lane & 15)) * AST + ((lane >> 4) << 4);
    const uint32_t boff = 128 * AST +
        (uint32_t)(wn * 32 + ((lane & 7) | ((lane >> 1) & 8))) * AST +
        (((lane >> 3) & 1) << 4);

    load_stage(0, 0);
    load_stage(1, 1);

    // ---- phase 1: correction passes ----
    uint32_t hacc[4][4][2];
    int      iacc[4][4][4];
    if (PASSES == 3) {
#pragma unroll
        for (int i = 0; i < 4; ++i)
#pragma unroll
            for (int j = 0; j < 4; ++j) { hacc[i][j][0] = 0u; hacc[i][j][1] = 0u; }
    }
    if (PASSES == 4) {
#pragma unroll
        for (int i = 0; i < 4; ++i)
#pragma unroll
            for (int j = 0; j < 4; ++j)
#pragma unroll
                for (int r = 0; r < 4; ++r) iacc[i][j][r] = 0;
    }

    for (int step = 0; step < corr; ++step) {
        asm volatile("cp.async.wait_group 1;" ::: "memory");
        __syncthreads();
        load_stage((step + 2) % 3, step + 2);
        const uint32_t sbase = sb + (step % 3) * STG;
#pragma unroll
        for (int kh = 0; kh < 4; ++kh) {
            const uint32_t ko = kh * 32;
            uint32_t af[4][4], bf[4][2];
#pragma unroll
            for (int mt = 0; mt < 4; ++mt)
                ldm4(af[mt], sbase + aoff + (uint32_t)mt * 16 * AST + ko);
#pragma unroll
            for (int np = 0; np < 2; ++np) {
                uint32_t r[4];
                ldm4(r, sbase + boff + (uint32_t)np * 16 * AST + ko);
                bf[np * 2][0] = r[0];      bf[np * 2][1] = r[1];
                bf[np * 2 + 1][0] = r[2];  bf[np * 2 + 1][1] = r[3];
            }
#pragma unroll
            for (int mt = 0; mt < 4; ++mt)
#pragma unroll
                for (int nt = 0; nt < 4; ++nt) {
                    if (PASSES == 4) mma16832s8(iacc[mt][nt], af[mt], bf[nt]);
                    else             mma16816h(hacc[mt][nt], af[mt], bf[nt]);
                }
        }
    }

    // ---- convert correction accumulators to fp32 ----
    float acc[4][4][4];
#pragma unroll
    for (int i = 0; i < 4; ++i)
#pragma unroll
        for (int j = 0; j < 4; ++j) {
            if (PASSES == 3) {
                const __half2 h0 = *reinterpret_cast<const __half2*>(&hacc[i][j][0]);
                const __half2 h1 = *reinterpret_cast<const __half2*>(&hacc[i][j][1]);
                acc[i][j][0] = __low2float(h0);  acc[i][j][1] = __high2float(h0);
                acc[i][j][2] = __low2float(h1);  acc[i][j][3] = __high2float(h1);
            } else if (PASSES == 4) {
#pragma unroll
                for (int r = 0; r < 4; ++r)
                    acc[i][j][r] = (float)iacc[i][j][r] * S_COMB;
            } else {
#pragma unroll
                for (int r = 0; r < 4; ++r) acc[i][j][r] = 0.0f;
            }
        }

    // ---- phase 2: hi·hi pass, fp32 accumulate ----
    for (int step = corr; step < total; ++step) {
        asm volatile("cp.async.wait_group 1;" ::: "memory");
        __syncthreads();
        load_stage((step + 2) % 3, step + 2);
        const uint32_t sbase = sb + (step % 3) * STG;
#pragma unroll
        for (int kh = 0; kh < 4; ++kh) {
            const uint32_t ko = kh * 32;
            uint32_t af[4][4], bf[4][2];
#pragma unroll
            for (int mt = 0; mt < 4; ++mt)
                ldm4(af[mt], sbase + aoff + (uint32_t)mt * 16 * AST + ko);
#pragma unroll
            for (int np = 0; np < 2; ++np) {
                uint32_t r[4];
                ldm4(r, sbase + boff + (uint32_t)np * 16 * AST + ko);
                bf[np * 2][0] = r[0];      bf[np * 2][1] = r[1];
                bf[np * 2 + 1][0] = r[2];  bf[np * 2 + 1][1] = r[3];
            }
#pragma unroll
            for (int mt = 0; mt < 4; ++mt)
#pragma unroll
                for (int nt = 0; nt < 4; ++nt)
                    mma16816(acc[mt][nt], af[mt], bf[nt]);
        }
    }

    // ---- epilogue ----
#pragma unroll
    for (int mt = 0; mt < 4; ++mt) {
        const int r0 = m0 + wm * 64 + mt * 16 + g;
        const int r1 = r0 + 8;
#pragma unroll
        for (int nt = 0; nt < 4; ++nt) {
            const int col = n0 + wn * 32 + nt * 8 + 2 * t;
            float v00 = acc[mt][nt][0], v01 = acc[mt][nt][1];
            float v10 = acc[mt][nt][2], v11 = acc[mt][nt][3];
            if (BIAS == 1) {
                const float b0 = gb.bias[col], b1 = gb.bias[col + 1];
                v00 += b0; v01 += b1; v10 += b0; v11 += b1;
            } else if (BIAS == 2) {
                const float b0 = gb.bias[r0], b1 = gb.bias[r1];
                v00 += b0; v01 += b0; v10 += b1; v11 += b1;
            }
            if (OUT_MODE == 0) {
                *reinterpret_cast<float2*>(&gb.Cf[(size_t)r0 * ldc + col]) = make_float2(v00, v01);
                *reinterpret_cast<float2*>(&gb.Cf[(size_t)r1 * ldc + col]) = make_float2(v10, v11);
            } else {
                __half2 lo0, lo1;
                __half2 hi0 = split_hi(v00, v01, lo0);
                __half2 hi1 = split_hi(v10, v11, lo1);
                __half2* p0 = reinterpret_cast<__half2*>(&gb.Ch[(size_t)r0 * ldc + col]);
                __half2* p1 = reinterpret_cast<__half2*>(&gb.Ch[(size_t)r1 * ldc + col]);
                p0[0] = hi0;  p0[lo_off / 2] = lo0;
                p1[0] = hi1;  p1[lo_off / 2] = lo1;
                if (EMIT8) {
                    const float l00 = __low2float(lo0), l01 = __high2float(lo0);
                    const float l10 = __low2float(lo1), l11 = __high2float(lo1);
                    char2 h8a = { q8clamp(v00, S8_HI), q8clamp(v01, S8_HI) };
                    char2 h8b = { q8clamp(v10, S8_HI), q8clamp(v11, S8_HI) };
                    char2 l8a = { q8clamp(l00, S8_LO), q8clamp(l01, S8_LO) };
                    char2 l8b = { q8clamp(l10, S8_LO), q8clamp(l11, S8_LO) };
                    *reinterpret_cast<char2*>(&gb.C8[(size_t)r0 * ldc + col])          = h8a;
                    *reinterpret_cast<char2*>(&gb.C8[(size_t)r1 * ldc + col])          = h8b;
                    *reinterpret_cast<char2*>(&gb.C8[(size_t)r0 * ldc + lo_off + col]) = l8a;
                    *reinterpret_cast<char2*>(&gb.C8[(size_t)r1 * ldc + lo_off + col]) = l8b;
                }
            }
        }
    }
}

// ---------------------------------------------------------------------------
// fp32 [R,C] -> split fp16 [R,2C]
// ---------------------------------------------------------------------------
__global__ __launch_bounds__(256)
void convert_split(const float* __restrict__ in, __half* __restrict__ out,
                   int C, size_t total)
{
    size_t i = ((size_t)blockIdx.x * 256 + threadIdx.x) * 4;
    if (i >= total) return;
    float4 v = *reinterpret_cast<const float4*>(&in[i]);
    size_t r = i / C;
    int c = (int)(i - r * C);
    __half2 lo0, lo1;
    __half2 hi0 = split_hi(v.x, v.y, lo0);
    __half2 hi1 = split_hi(v.z, v.w, lo1);
    __half* row = out + r * (2 * (size_t)C);
    *reinterpret_cast<__half2*>(&row[c])         = hi0;
    *reinterpret_cast<__half2*>(&row[c + 2])     = hi1;
    *reinterpret_cast<__half2*>(&row[C + c])     = lo0;
    *reinterpret_cast<__half2*>(&row[C + c + 2]) = lo1;
}

// ---------------------------------------------------------------------------
// All 7 weight transposes in ONE launch: in[R,C] -> split fp16 out[C,2R].
// ---------------------------------------------------------------------------
__global__ __launch_bounds__(256)
void weight_prep(const float* w0, const float* w1, const float* w2c,
                 const float* w3, const float* w4, const float* w5,
                 const float* w6,
                 __half* o0, __half* o1, __half* o2, __half* o3,
                 __half* o4, __half* o5, __half* o6)
{
    const float* src; __half* dst; int R, C;
    switch (blockIdx.z) {
        case 0: src = w0; dst = o0; R = DC; C = DC; break;
        case 1: src = w1; dst = o1; R = DC; C = DC; break;
        case 2: src = w2c; dst = o2; R = DC; C = DC; break;
        case 3: src = w3; dst = o3; R = DC; C = DC; break;
        case 4: src = w4; dst = o4; R = DC; C = DC; break;
        case 5: src = w5; dst = o5; R = DC; C = DC; break;
        default: src = w6; dst = o6; R = 2 * DC; C = 2 * DC; break;
    }
    const int bx = blockIdx.x * 32, by = blockIdx.y * 32;
    if (bx >= C || by >= R) return;

    __shared__ float tl[32][33];
    const int tx = threadIdx.x, ty = threadIdx.y;
#pragma unroll
    for (int j = ty; j < 32; j += 8)
        tl[j][tx] = src[(size_t)(by + j) * C + bx + tx];
    __syncthreads();
#pragma unroll
    for (int j = ty; j < 32; j += 8) {
        const float v = tl[tx][j];
        const __half h = __float2half_rn(v);
        const __half l = __float2half_rn(v - __half2float(h));
        __half* row = dst + (size_t)(bx + j) * (2 * (size_t)R);
        row[by + tx]     = h;
        row[R + by + tx] = l;
    }
}

// ---------------------------------------------------------------------------
// Row softmax (batched over blockIdx.y = branch): fp32 logits -> fp16 probs
// ---------------------------------------------------------------------------
__global__ __launch_bounds__(256)
void softmax_hi(const float* __restrict__ S, __half* __restrict__ S2)
{
    __shared__ float row[NR];
    __shared__ float red[256];
    const size_t off = (size_t)blockIdx.y * NR * NR + (size_t)blockIdx.x * NR;
    const float* p = S + off;
    __half* o = S2 + off;
    const int tid = threadIdx.x;

    float lmax = -3.0e38f;
    for (int i = tid * 4; i < NR; i += 1024) {
        float4 v = *reinterpret_cast<const float4*>(&p[i]);
        *reinterpret_cast<float4*>(&row[i]) = v;
        lmax = fmaxf(lmax, fmaxf(fmaxf(v.x, v.y), fmaxf(v.z, v.w)));
    }
    red[tid] = lmax;
    __syncthreads();
#pragma unroll
    for (int s = 128; s > 0; s >>= 1) {
        if (tid < s) red[tid] = fmaxf(red[tid], red[tid + s]);
        __syncthreads();
    }
    const float bmax = red[0];
    __syncthreads();

    float lsum = 0.0f;
    for (int i = tid * 4; i < NR; i += 1024) {
        float4 v = *reinterpret_cast<float4*>(&row[i]);
        v.x = __expf(v.x - bmax); v.y = __expf(v.y - bmax);
        v.z = __expf(v.z - bmax); v.w = __expf(v.w - bmax);
        lsum += v.x + v.y + v.z + v.w;
        *reinterpret_cast<float4*>(&row[i]) = v;
    }
    red[tid] = lsum;
    __syncthreads();
#pragma unroll
    for (int s = 128; s > 0; s >>= 1) {
        if (tid < s) red[tid] += red[tid + s];
        __syncthreads();
    }
    const float inv = 1.0f / red[0];
    __syncthreads();

    for (int i = tid * 4; i < NR; i += 1024) {
        float4 v = *reinterpret_cast<float4*>(&row[i]);
        *reinterpret_cast<__half2*>(&o[i]) =
            __halves2half2(__float2half_rn(v.x * inv), __float2half_rn(v.y * inv));
        *reinterpret_cast<__half2*>(&o[i + 2]) =
            __halves2half2(__float2half_rn(v.z * inv), __float2half_rn(v.w * inv));
    }
}

// ---------------------------------------------------------------------------
// Launch sequence
// ---------------------------------------------------------------------------
extern "C" void kernel_launch(void* const* d_in, const int* in_sizes, int n_in,
                              void* d_out, int out_size)
{
    const float* img = (const float*)d_in[0];
    const float* tab = (const float*)d_in[1];
    const float* Wqi = (const float*)d_in[2];  const float* bqi = (const float*)d_in[3];
    const float* Wkt = (const float*)d_in[4];  const float* bkt = (const float*)d_in[5];
    const float* Wvt = (const float*)d_in[6];  const float* bvt = (const float*)d_in[7];
    const float* Wqt = (const float*)d_in[8];  const float* bqt = (const float*)d_in[9];
    const float* Wki = (const float*)d_in[10]; const float* bki = (const float*)d_in[11];
    const float* Wvi = (const float*)d_in[12]; const float* bvi = (const float*)d_in[13];
    const float* Wo  = (const float*)d_in[14]; const float* bo  = (const float*)d_in[15];
    float* out = (float*)d_out;

    cudaFuncSetAttribute(hgemm3<0,0,4,0>, cudaFuncAttributeMaxDynamicSharedMemorySize, GSMEM);
    cudaFuncSetAttribute(hgemm3<0,1,1,0>, cudaFuncAttributeMaxDynamicSharedMemorySize, GSMEM);
    cudaFuncSetAttribute(hgemm3<1,0,1,0>, cudaFuncAttributeMaxDynamicSharedMemorySize, GSMEM);
    cudaFuncSetAttribute(hgemm3<1,1,3,1>, cudaFuncAttributeMaxDynamicSharedMemorySize, GSMEM);
    cudaFuncSetAttribute(hgemm3<1,2,1,0>, cudaFuncAttributeMaxDynamicSharedMemorySize, GSMEM);

    float *S;
    __half *img2, *tab2, *w2, *wo2, *qk2, *vt2, *S2, *fused2;
    int8_t *qk8;
    cudaGetSymbolAddress((void**)&S,      g_S);
    cudaGetSymbolAddress((void**)&img2,   g_img2);
    cudaGetSymbolAddress((void**)&tab2,   g_tab2);
    cudaGetSymbolAddress((void**)&w2,     g_w2);
    cudaGetSymbolAddress((void**)&wo2,    g_wo2);
    cudaGetSymbolAddress((void**)&qk2,    g_qk2);
    cudaGetSymbolAddress((void**)&qk8,    g_qk8);
    cudaGetSymbolAddress((void**)&vt2,    g_vt2);
    cudaGetSymbolAddress((void**)&S2,     g_S2);
    cudaGetSymbolAddress((void**)&fused2, g_fused2);

    const size_t W2SZ = (size_t)DC * 2 * DC;
    __half* wqi2 = w2 + 0 * W2SZ;  __half* wkt2 = w2 + 1 * W2SZ;
    __half* wvt2 = w2 + 2 * W2SZ;  __half* wqt2 = w2 + 3 * W2SZ;
    __half* wki2 = w2 + 4 * W2SZ;  __half* wvi2 = w2 + 5 * W2SZ;
    const size_t QK2 = (size_t)NR * 2 * DC;
    __half* q12 = qk2 + 0 * QK2;   __half* k12 = qk2 + 1 * QK2;
    __half* q22 = qk2 + 2 * QK2;   __half* k22 = qk2 + 3 * QK2;
    int8_t* q18 = qk8 + 0 * QK2;   int8_t* k18 = qk8 + 1 * QK2;
    int8_t* q28 = qk8 + 2 * QK2;   int8_t* k28 = qk8 + 3 * QK2;
    __half* v1t2 = vt2;            __half* v2t2 = vt2 + (size_t)DC * 2 * NR;
    float*  S_1 = S;               float*  S_2 = S + (size_t)NR * NR;
    __half* P_1 = S2;              __half* P_2 = S2 + (size_t)NR * NR;

    // ---- launches 0-2: input conversions + combined weight prep ----
    const size_t tot = (size_t)NR * DC;
    convert_split<<<(unsigned)((tot / 4 + 255) / 256), 256>>>(img, img2, DC, tot);
    convert_split<<<(unsigned)((tot / 4 + 255) / 256), 256>>>(tab, tab2, DC, tot);
    weight_prep<<<dim3(64, 64, 7), dim3(32, 8)>>>(
        Wqi, Wkt, Wvt, Wqt, Wki, Wvi, Wo,
        wqi2, wkt2, wvt2, wqt2, wki2, wvi2, wo2);

    // ---- launch 3: all 4 Q/K projections (3-pass + int8 emission) ----
    {
        GB4 b = {{ { img2, wqi2, nullptr, nullptr, bqi, nullptr, q12, q18 },
                   { tab2, wkt2, nullptr, nullptr, bkt, nullptr, k12, k18 },
                   { tab2, wqt2, nullptr, nullptr, bqt, nullptr, q22, q28 },
                   { img2, wki2, nullptr, nullptr, bki, nullptr, k22, k28 } }};
        hgemm3<1,1,3,1><<<dim3(DC/128, NR/128, 4), TPB, GSMEM>>>(
            b, DC, 2*DC, 2*DC, 0, 2*DC, DC);
    }
    // ---- launch 4: both V^T projections (1-pass) ----
    {
        GB4 b = {{ { wvt2, tab2, nullptr, nullptr, bvt, nullptr, v1t2, nullptr },
                   { wvi2, img2, nullptr, nullptr, bvi, nullptr, v2t2, nullptr },
                   {}, {} }};
        hgemm3<1,2,1,0><<<dim3(NR/128, DC/128, 2), TPB, GSMEM>>>(
            b, DC, 2*DC, 2*DC, 0, 2*NR, NR);
    }
    // ---- launch 5: both QK^T (int8 corrections + fp16 hi·hi) ----
    {
        GB4 b = {{ { q12, k12, q18, k18, nullptr, S_1, nullptr, nullptr },
                   { q22, k22, q28, k28, nullptr, S_2, nullptr, nullptr },
                   {}, {} }};
        hgemm3<0,0,4,0><<<dim3(NR/128, NR/128, 2), TPB, GSMEM>>>(
            b, DC, 2*DC, 2*DC, 2*DC, NR, 0);
    }
    // ---- launch 6: both softmaxes ----
    softmax_hi<<<dim3(NR, 2), 256>>>(S, S2);
    // ---- launch 7: both P·V (1-pass) ----
    {
        GB4 b = {{ { P_1, v1t2, nullptr, nullptr, nullptr, nullptr, fused2 + DC, nullptr },
                   { P_2, v2t2, nullptr, nullptr, nullptr, nullptr, fused2, nullptr },
                   {}, {} }};
        hgemm3<1,0,1,0><<<dim3(DC/128, NR/128, 2), TPB, GSMEM>>>(
            b, NR, NR, 2*NR, 0, 4*DC, 2*DC);
    }
    // ---- launch 8: output projection (1-pass, fp32 out) ----
    {
        GB4 b = {{ { fused2, wo2, nullptr, nullptr, bo, out, nullptr, nullptr },
                   {}, {}, {} }};
        hgemm3<0,1,1,0><<<dim3(2*DC/128, NR/128, 1), TPB, GSMEM>>>(
            b, 2*DC, 4*DC, 4*DC, 0, 2*DC, 0);
    }
}

// round 11
// speedup vs baseline: 1.5861x; 1.0610x over previous
#include <cuda_runtime.h>
#include <cuda_fp16.h>
#include <cstdint>

#define NR 8192
#define DC 1024

// int8 scales. Q/K (sigma~0.64): hi 2^5, lo 2^16 -> product 2^-21.
// Inputs x (sigma~1):  hi 2^4,  lo 2^14.   Weights (sigma=0.02): hi 2^10, lo 2^20.
// Both projection sweeps share product scale 2^-24.
#define S8_HI 32.0f
#define S8_LO 65536.0f
#define SCOMB_QK   (1.0f / 2097152.0f)     // 2^-21
#define SIN_HI 16.0f
#define SIN_LO 16384.0f
#define SW_HI  1024.0f
#define SW_LO  1048576.0f
#define SCOMB_PROJ (1.0f / 16777216.0f)    // 2^-24

// ---------------------------------------------------------------------------
// Static device scratch. Split-fp16 tensors stored [rows, 2K]: hi | lo.
// ---------------------------------------------------------------------------
__device__ float  g_S[(size_t)2 * NR * NR];             // logits (branch 0/1)
__device__ __half g_img2[(size_t)NR * 2 * DC];
__device__ __half g_tab2[(size_t)NR * 2 * DC];
__device__ int8_t g_in8[(size_t)2 * NR * 2 * DC];       // img8, tab8 (hi|lo)
__device__ __half g_w2[(size_t)6 * DC * 2 * DC];        // 6x W^T [1024,2048]
__device__ int8_t g_w8[(size_t)6 * DC * 2 * DC];        // 6x W^T int8 (hi|lo)
__device__ __half g_wo2[(size_t)2 * DC * 4 * DC];       // Wo^T [2048,4096]
__device__ __half g_qk2[(size_t)4 * NR * 2 * DC];       // q1,k1,q2,k2 fp16 hi|lo
__device__ int8_t g_qk8[(size_t)4 * NR * 2 * DC];       // q1,k1,q2,k2 int8 hi|lo
__device__ __half g_vt2[(size_t)2 * DC * 2 * NR];       // v1^T,v2^T
__device__ __half g_S2[(size_t)2 * NR * NR];            // probs hi-only, 2 branches
__device__ __half g_fused2[(size_t)NR * 4 * DC];        // fused split [8192,4096]

// ---------------------------------------------------------------------------
// helpers
// ---------------------------------------------------------------------------
__device__ __forceinline__ uint32_t smem_u32(const void* p) {
    uint32_t a;
    asm("{ .reg .u64 t; cvta.to.shared.u64 t, %1; cvt.u32.u64 %0, t; }" : "=r"(a) : "l"(p));
    return a;
}
__device__ __forceinline__ void cp16(uint32_t d, const void* g) {
    asm volatile("cp.async.cg.shared.global [%0], [%1], 16;"
                 :: "r"(d), "l"(__cvta_generic_to_global(g)) : "memory");
}
__device__ __forceinline__ void ldm4(uint32_t* r, uint32_t a) {
    asm volatile("ldmatrix.sync.aligned.m8n8.x4.shared.b16 {%0,%1,%2,%3}, [%4];"
                 : "=r"(r[0]), "=r"(r[1]), "=r"(r[2]), "=r"(r[3]) : "r"(a));
}
__device__ __forceinline__ void mma16816(float* d, const uint32_t* a, const uint32_t* b) {
    asm("mma.sync.aligned.m16n8k16.row.col.f32.f16.f16.f32 "
        "{%0,%1,%2,%3}, {%4,%5,%6,%7}, {%8,%9}, {%0,%1,%2,%3};"
        : "+f"(d[0]), "+f"(d[1]), "+f"(d[2]), "+f"(d[3])
        : "r"(a[0]), "r"(a[1]), "r"(a[2]), "r"(a[3]), "r"(b[0]), "r"(b[1]));
}
__device__ __forceinline__ void mma16832s8(int* d, const uint32_t* a, const uint32_t* b) {
    asm("mma.sync.aligned.m16n8k32.row.col.s32.s8.s8.s32 "
        "{%0,%1,%2,%3}, {%4,%5,%6,%7}, {%8,%9}, {%0,%1,%2,%3};"
        : "+r"(d[0]), "+r"(d[1]), "+r"(d[2]), "+r"(d[3])
        : "r"(a[0]), "r"(a[1]), "r"(a[2]), "r"(a[3]), "r"(b[0]), "r"(b[1]));
}
__device__ __forceinline__ __half2 split_hi(float x0, float x1, __half2& lo) {
    __half h0 = __float2half_rn(x0), h1 = __float2half_rn(x1);
    lo = __halves2half2(__float2half_rn(x0 - __half2float(h0)),
                        __float2half_rn(x1 - __half2float(h1)));
    return __halves2half2(h0, h1);
}
__device__ __forceinline__ int8_t q8clamp(float x, float s) {
    int v = __float2int_rn(x * s);
    v = v > 127 ? 127 : (v < -127 ? -127 : v);
    return (int8_t)v;
}

// ---------------------------------------------------------------------------
// Batched split NT GEMM:  C[M,N] = A[M,K] . B[N,K]^T per blockIdx.z
// PASSES=4: INT8 corrections (2 sweeps: Ahi8·Blo8 then Alo8·Bhi8, shared s32
//           accumulator, k=128/step) + fp16 hi·hi pass (fp32 acc).
// PASSES=1: hi·hi only.
// Tile 128x128, 256 threads (8 warps 2x4, 64x32 each), cp.async 3-stage.
// OUT_MODE: 0 = fp32 to Cf, 1 = split fp16 to Ch.  EMIT8: also emit int8 hi|lo.
// BIAS: 0 none, 1 per-column, 2 per-row
// ---------------------------------------------------------------------------
#define TPB 256
#define AST 144                       // 128B data + 16B pad (36 banks/row)
#define STG (128 * AST * 2)           // 36864 B per stage (A+B)
#define GSMEM (3 * STG)               // 110592 B

struct GB { const __half* A; const __half* B; const int8_t* A8; const int8_t* B8;
            const float* bias; float* Cf; __half* Ch; int8_t* C8; };
struct GB4 { GB g[4]; };

template <int OUT_MODE, int BIAS, int PASSES, int EMIT8>
__global__ __launch_bounds__(TPB, 2)
void hgemm3(const __grid_constant__ GB4 batch, int K,
            size_t ldA, size_t ldB, size_t ld8, int ldc, int lo_off, float s_comb)
{
    extern __shared__ char smc[];
    const uint32_t sb = smem_u32(smc);
    const GB gb = batch.g[blockIdx.z];
    const int tid = threadIdx.x;
    const int wid = tid >> 5, lane = tid & 31;
    const int g = lane >> 2, t = lane & 3;
    const int wm = wid & 1, wn = wid >> 1;          // 2x4 warp grid, 64x32 each
    const int m0 = blockIdx.y * 128, n0 = blockIdx.x * 128;

    const int K64 = K >> 6;
    const int corr  = (PASSES == 4) ? K64 : 0;      // int8 steps (k=128 each, 2 sweeps)
    const int total = corr + K64;

    const int lr = tid >> 3;              // 0..31 (row base, step 32)
    const int lc  = (tid & 7) * 8;        // half offset within 64-col fp16 row
    const int lcB = (tid & 7) * 16;       // byte offset

    auto load_stage = [&](int s, int step) {
        if (step < total) {
            const uint32_t da = sb + s * STG + lr * AST + lcB;
            const uint32_t db = da + 128 * AST;
            if (PASSES == 4 && step < corr) {
                const int spw = K >> 7;              // steps per sweep
                const int swp = step / spw, kk = step - swp * spw;
                const int a8o = swp ? K : 0;         // sweep0: Ahi·Blo, sweep1: Alo·Bhi
                const int b8o = swp ? 0 : K;
                const int8_t* ga  = gb.A8 + (size_t)(m0 + lr) * ld8 + a8o + kk * 128 + lcB;
                const int8_t* gbp = gb.B8 + (size_t)(n0 + lr) * ld8 + b8o + kk * 128 + lcB;
#pragma unroll
                for (int i = 0; i < 4; ++i) {
                    cp16(da + i * 32 * AST, ga  + (size_t)i * 32 * ld8);
                    cp16(db + i * 32 * AST, gbp + (size_t)i * 32 * ld8);
                }
            } else {
                const int kk = step - corr;
                const __half* ga  = gb.A + (size_t)(m0 + lr) * ldA + (size_t)kk * 64 + lc;
                const __half* gbp = gb.B + (size_t)(n0 + lr) * ldB + (size_t)kk * 64 + lc;
#pragma unroll
                for (int i = 0; i < 4; ++i) {
                    cp16(da + i * 32 * AST, ga  + (size_t)i * 32 * ldA);
                    cp16(db + i * 32 * AST, gbp + (size_t)i * 32 * ldB);
                }
            }
        }
        asm volatile("cp.async.commit_group;" ::: "memory");
    };

    // ldmatrix per-lane offsets within a stage (identical for fp16 and int8)
    const uint32_t aoff = (uint32_t)(wm * 64 + (lane & 15)) * AST + ((lane >> 4) << 4);
    const uint32_t boff = 128 * AST +
        (uint32_t)(wn * 32 + ((lane & 7) | ((lane >> 1) & 8))) * AST +
        (((lane >> 3) & 1) << 4);

    load_stage(0, 0);
    load_stage(1, 1);

    // ---- phase 1: int8 correction sweeps, shared s32 accumulator ----
    int iacc[4][4][4];
    if (PASSES == 4) {
#pragma unroll
        for (int i = 0; i < 4; ++i)
#pragma unroll
            for (int j = 0; j < 4; ++j)
#pragma unroll
                for (int r = 0; r < 4; ++r) iacc[i][j][r] = 0;
    }

    for (int step = 0; step < corr; ++step) {
        asm volatile("cp.async.wait_group 1;" ::: "memory");
        __syncthreads();
        load_stage((step + 2) % 3, step + 2);
        const uint32_t sbase = sb + (step % 3) * STG;
#pragma unroll
        for (int kh = 0; kh < 4; ++kh) {
            const uint32_t ko = kh * 32;
            uint32_t af[4][4], bf[4][2];
#pragma unroll
            for (int mt = 0; mt < 4; ++mt)
                ldm4(af[mt], sbase + aoff + (uint32_t)mt * 16 * AST + ko);
#pragma unroll
            for (int np = 0; np < 2; ++np) {
                uint32_t r[4];
                ldm4(r, sbase + boff + (uint32_t)np * 16 * AST + ko);
                bf[np * 2][0] = r[0];      bf[np * 2][1] = r[1];
                bf[np * 2 + 1][0] = r[2];  bf[np * 2 + 1][1] = r[3];
            }
#pragma unroll
            for (int mt = 0; mt < 4; ++mt)
#pragma unroll
                for (int nt = 0; nt < 4; ++nt)
                    mma16832s8(iacc[mt][nt], af[mt], bf[nt]);
        }
    }

    // ---- convert correction accumulators to fp32 ----
    float acc[4][4][4];
#pragma unroll
    for (int i = 0; i < 4; ++i)
#pragma unroll
        for (int j = 0; j < 4; ++j) {
            if (PASSES == 4) {
#pragma unroll
                for (int r = 0; r < 4; ++r)
                    acc[i][j][r] = (float)iacc[i][j][r] * s_comb;
            } else {
#pragma unroll
                for (int r = 0; r < 4; ++r) acc[i][j][r] = 0.0f;
            }
        }

    // ---- phase 2: hi·hi pass, fp32 accumulate ----
    for (int step = corr; step < total; ++step) {
        asm volatile("cp.async.wait_group 1;" ::: "memory");
        __syncthreads();
        load_stage((step + 2) % 3, step + 2);
        const uint32_t sbase = sb + (step % 3) * STG;
#pragma unroll
        for (int kh = 0; kh < 4; ++kh) {
            const uint32_t ko = kh * 32;
            uint32_t af[4][4], bf[4][2];
#pragma unroll
            for (int mt = 0; mt < 4; ++mt)
                ldm4(af[mt], sbase + aoff + (uint32_t)mt * 16 * AST + ko);
#pragma unroll
            for (int np = 0; np < 2; ++np) {
                uint32_t r[4];
                ldm4(r, sbase + boff + (uint32_t)np * 16 * AST + ko);
                bf[np * 2][0] = r[0];      bf[np * 2][1] = r[1];
                bf[np * 2 + 1][0] = r[2];  bf[np * 2 + 1][1] = r[3];
            }
#pragma unroll
            for (int mt = 0; mt < 4; ++mt)
#pragma unroll
                for (int nt = 0; nt < 4; ++nt)
                    mma16816(acc[mt][nt], af[mt], bf[nt]);
        }
    }

    // ---- epilogue ----
#pragma unroll
    for (int mt = 0; mt < 4; ++mt) {
        const int r0 = m0 + wm * 64 + mt * 16 + g;
        const int r1 = r0 + 8;
#pragma unroll
        for (int nt = 0; nt < 4; ++nt) {
            const int col = n0 + wn * 32 + nt * 8 + 2 * t;
            float v00 = acc[mt][nt][0], v01 = acc[mt][nt][1];
            float v10 = acc[mt][nt][2], v11 = acc[mt][nt][3];
            if (BIAS == 1) {
                const float b0 = gb.bias[col], b1 = gb.bias[col + 1];
                v00 += b0; v01 += b1; v10 += b0; v11 += b1;
            } else if (BIAS == 2) {
                const float b0 = gb.bias[r0], b1 = gb.bias[r1];
                v00 += b0; v01 += b0; v10 += b1; v11 += b1;
            }
            if (OUT_MODE == 0) {
                *reinterpret_cast<float2*>(&gb.Cf[(size_t)r0 * ldc + col]) = make_float2(v00, v01);
                *reinterpret_cast<float2*>(&gb.Cf[(size_t)r1 * ldc + col]) = make_float2(v10, v11);
            } else {
                __half2 lo0, lo1;
                __half2 hi0 = split_hi(v00, v01, lo0);
                __half2 hi1 = split_hi(v10, v11, lo1);
                __half2* p0 = reinterpret_cast<__half2*>(&gb.Ch[(size_t)r0 * ldc + col]);
                __half2* p1 = reinterpret_cast<__half2*>(&gb.Ch[(size_t)r1 * ldc + col]);
                p0[0] = hi0;  p0[lo_off / 2] = lo0;
                p1[0] = hi1;  p1[lo_off / 2] = lo1;
                if (EMIT8) {
                    const float l00 = __low2float(lo0), l01 = __high2float(lo0);
                    const float l10 = __low2float(lo1), l11 = __high2float(lo1);
                    char2 h8a = { q8clamp(v00, S8_HI), q8clamp(v01, S8_HI) };
                    char2 h8b = { q8clamp(v10, S8_HI), q8clamp(v11, S8_HI) };
                    char2 l8a = { q8clamp(l00, S8_LO), q8clamp(l01, S8_LO) };
                    char2 l8b = { q8clamp(l10, S8_LO), q8clamp(l11, S8_LO) };
                    *reinterpret_cast<char2*>(&gb.C8[(size_t)r0 * ldc + col])          = h8a;
                    *reinterpret_cast<char2*>(&gb.C8[(size_t)r1 * ldc + col])          = h8b;
                    *reinterpret_cast<char2*>(&gb.C8[(size_t)r0 * ldc + lo_off + col]) = l8a;
                    *reinterpret_cast<char2*>(&gb.C8[(size_t)r1 * ldc + lo_off + col]) = l8b;
                }
            }
        }
    }
}

// ---------------------------------------------------------------------------
// fp32 [R,C] -> split fp16 [R,2C] + int8 [R,2C] (hi@2^4 | lo@2^14)
// ---------------------------------------------------------------------------
__global__ __launch_bounds__(256)
void convert_split(const float* __restrict__ in, __half* __restrict__ out,
                   int8_t* __restrict__ out8, int C, size_t total)
{
    size_t i = ((size_t)blockIdx.x * 256 + threadIdx.x) * 4;
    if (i >= total) return;
    float4 v = *reinterpret_cast<const float4*>(&in[i]);
    size_t r = i / C;
    int c = (int)(i - r * C);
    __half2 lo0, lo1;
    __half2 hi0 = split_hi(v.x, v.y, lo0);
    __half2 hi1 = split_hi(v.z, v.w, lo1);
    __half* row = out + r * (2 * (size_t)C);
    *reinterpret_cast<__half2*>(&row[c])         = hi0;
    *reinterpret_cast<__half2*>(&row[c + 2])     = hi1;
    *reinterpret_cast<__half2*>(&row[C + c])     = lo0;
    *reinterpret_cast<__half2*>(&row[C + c + 2]) = lo1;
    int8_t* row8 = out8 + r * (2 * (size_t)C);
    char4 h8 = { q8clamp(__low2float(hi0), SIN_HI), q8clamp(__high2float(hi0), SIN_HI),
                 q8clamp(__low2float(hi1), SIN_HI), q8clamp(__high2float(hi1), SIN_HI) };
    char4 l8 = { q8clamp(__low2float(lo0), SIN_LO), q8clamp(__high2float(lo0), SIN_LO),
                 q8clamp(__low2float(lo1), SIN_LO), q8clamp(__high2float(lo1), SIN_LO) };
    *reinterpret_cast<char4*>(&row8[c])     = h8;
    *reinterpret_cast<char4*>(&row8[C + c]) = l8;
}

// ---------------------------------------------------------------------------
// All 7 weight transposes in ONE launch: in[R,C] -> split fp16 out[C,2R],
// plus int8 (hi@2^10 | lo@2^20) for the 6 projection weights (z<6).
// ---------------------------------------------------------------------------
__global__ __launch_bounds__(256)
void weight_prep(const float* w0, const float* w1, const float* w2c,
                 const float* w3, const float* w4, const float* w5,
                 const float* w6,
                 __half* o0, __half* o1, __half* o2, __half* o3,
                 __half* o4, __half* o5, __half* o6, int8_t* o8base)
{
    const float* src; __half* dst; int R, C;
    switch (blockIdx.z) {
        case 0: src = w0; dst = o0; R = DC; C = DC; break;
        case 1: src = w1; dst = o1; R = DC; C = DC; break;
        case 2: src = w2c; dst = o2; R = DC; C = DC; break;
        case 3: src = w3; dst = o3; R = DC; C = DC; break;
        case 4: src = w4; dst = o4; R = DC; C = DC; break;
        case 5: src = w5; dst = o5; R = DC; C = DC; break;
        default: src = w6; dst = o6; R = 2 * DC; C = 2 * DC; break;
    }
    const int bx = blockIdx.x * 32, by = blockIdx.y * 32;
    if (bx >= C || by >= R) return;
    int8_t* dst8 = (blockIdx.z < 6)
        ? o8base + (size_t)blockIdx.z * DC * 2 * DC : nullptr;

    __shared__ float tl[32][33];
    const int tx = threadIdx.x, ty = threadIdx.y;
#pragma unroll
    for (int j = ty; j < 32; j += 8)
        tl[j][tx] = src[(size_t)(by + j) * C + bx + tx];
    __syncthreads();
#pragma unroll
    for (int j = ty; j < 32; j += 8) {
        const float v = tl[tx][j];
        const __half h = __float2half_rn(v);
        const float hf = __half2float(h);
        const __half l = __float2half_rn(v - hf);
        __half* row = dst + (size_t)(bx + j) * (2 * (size_t)R);
        row[by + tx]     = h;
        row[R + by + tx] = l;
        if (dst8) {
            int8_t* row8 = dst8 + (size_t)(bx + j) * (2 * (size_t)R);
            row8[by + tx]     = q8clamp(hf, SW_HI);
            row8[R + by + tx] = q8clamp(__half2float(l), SW_LO);
        }
    }
}

// ---------------------------------------------------------------------------
// Row softmax (batched over blockIdx.y = branch): fp32 logits -> fp16 probs
// ---------------------------------------------------------------------------
__global__ __launch_bounds__(256)
void softmax_hi(const float* __restrict__ S, __half* __restrict__ S2)
{
    __shared__ float row[NR];
    __shared__ float red[256];
    const size_t off = (size_t)blockIdx.y * NR * NR + (size_t)blockIdx.x * NR;
    const float* p = S + off;
    __half* o = S2 + off;
    const int tid = threadIdx.x;

    float lmax = -3.0e38f;
    for (int i = tid * 4; i < NR; i += 1024) {
        float4 v = *reinterpret_cast<const float4*>(&p[i]);
        *reinterpret_cast<float4*>(&row[i]) = v;
        lmax = fmaxf(lmax, fmaxf(fmaxf(v.x, v.y), fmaxf(v.z, v.w)));
    }
    red[tid] = lmax;
    __syncthreads();
#pragma unroll
    for (int s = 128; s > 0; s >>= 1) {
        if (tid < s) red[tid] = fmaxf(red[tid], red[tid + s]);
        __syncthreads();
    }
    const float bmax = red[0];
    __syncthreads();

    float lsum = 0.0f;
    for (int i = tid * 4; i < NR; i += 1024) {
        float4 v = *reinterpret_cast<float4*>(&row[i]);
        v.x = __expf(v.x - bmax); v.y = __expf(v.y - bmax);
        v.z = __expf(v.z - bmax); v.w = __expf(v.w - bmax);
        lsum += v.x + v.y + v.z + v.w;
        *reinterpret_cast<float4*>(&row[i]) = v;
    }
    red[tid] = lsum;
    __syncthreads();
#pragma unroll
    for (int s = 128; s > 0; s >>= 1) {
        if (tid < s) red[tid] += red[tid + s];
        __syncthreads();
    }
    const float inv = 1.0f / red[0];
    __syncthreads();

    for (int i = tid * 4; i < NR; i += 1024) {
        float4 v = *reinterpret_cast<float4*>(&row[i]);
        *reinterpret_cast<__half2*>(&o[i]) =
            __halves2half2(__float2half_rn(v.x * inv), __float2half_rn(v.y * inv));
        *reinterpret_cast<__half2*>(&o[i + 2]) =
            __halves2half2(__float2half_rn(v.z * inv), __float2half_rn(v.w * inv));
    }
}

// ---------------------------------------------------------------------------
// Launch sequence
// ---------------------------------------------------------------------------
extern "C" void kernel_launch(void* const* d_in, const int* in_sizes, int n_in,
                              void* d_out, int out_size)
{
    const float* img = (const float*)d_in[0];
    const float* tab = (const float*)d_in[1];
    const float* Wqi = (const float*)d_in[2];  const float* bqi = (const float*)d_in[3];
    const float* Wkt = (const float*)d_in[4];  const float* bkt = (const float*)d_in[5];
    const float* Wvt = (const float*)d_in[6];  const float* bvt = (const float*)d_in[7];
    const float* Wqt = (const float*)d_in[8];  const float* bqt = (const float*)d_in[9];
    const float* Wki = (const float*)d_in[10]; const float* bki = (const float*)d_in[11];
    const float* Wvi = (const float*)d_in[12]; const float* bvi = (const float*)d_in[13];
    const float* Wo  = (const float*)d_in[14]; const float* bo  = (const float*)d_in[15];
    float* out = (float*)d_out;

    cudaFuncSetAttribute(hgemm3<0,0,4,0>, cudaFuncAttributeMaxDynamicSharedMemorySize, GSMEM);
    cudaFuncSetAttribute(hgemm3<0,1,1,0>, cudaFuncAttributeMaxDynamicSharedMemorySize, GSMEM);
    cudaFuncSetAttribute(hgemm3<1,0,1,0>, cudaFuncAttributeMaxDynamicSharedMemorySize, GSMEM);
    cudaFuncSetAttribute(hgemm3<1,1,4,1>, cudaFuncAttributeMaxDynamicSharedMemorySize, GSMEM);
    cudaFuncSetAttribute(hgemm3<1,2,1,0>, cudaFuncAttributeMaxDynamicSharedMemorySize, GSMEM);

    float *S;
    __half *img2, *tab2, *w2, *wo2, *qk2, *vt2, *S2, *fused2;
    int8_t *qk8, *in8, *w8;
    cudaGetSymbolAddress((void**)&S,      g_S);
    cudaGetSymbolAddress((void**)&img2,   g_img2);
    cudaGetSymbolAddress((void**)&tab2,   g_tab2);
    cudaGetSymbolAddress((void**)&in8,    g_in8);
    cudaGetSymbolAddress((void**)&w2,     g_w2);
    cudaGetSymbolAddress((void**)&w8,     g_w8);
    cudaGetSymbolAddress((void**)&wo2,    g_wo2);
    cudaGetSymbolAddress((void**)&qk2,    g_qk2);
    cudaGetSymbolAddress((void**)&qk8,    g_qk8);
    cudaGetSymbolAddress((void**)&vt2,    g_vt2);
    cudaGetSymbolAddress((void**)&S2,     g_S2);
    cudaGetSymbolAddress((void**)&fused2, g_fused2);

    const size_t W2SZ = (size_t)DC * 2 * DC;
    __half* wqi2 = w2 + 0 * W2SZ;  __half* wkt2 = w2 + 1 * W2SZ;
    __half* wvt2 = w2 + 2 * W2SZ;  __half* wqt2 = w2 + 3 * W2SZ;
    __half* wki2 = w2 + 4 * W2SZ;  __half* wvi2 = w2 + 5 * W2SZ;
    int8_t* wqi8 = w8 + 0 * W2SZ;  int8_t* wkt8 = w8 + 1 * W2SZ;
    int8_t* wqt8 = w8 + 3 * W2SZ;  int8_t* wki8 = w8 + 4 * W2SZ;
    const size_t QK2 = (size_t)NR * 2 * DC;
    __half* q12 = qk2 + 0 * QK2;   __half* k12 = qk2 + 1 * QK2;
    __half* q22 = qk2 + 2 * QK2;   __half* k22 = qk2 + 3 * QK2;
    int8_t* q18 = qk8 + 0 * QK2;   int8_t* k18 = qk8 + 1 * QK2;
    int8_t* q28 = qk8 + 2 * QK2;   int8_t* k28 = qk8 + 3 * QK2;
    int8_t* img8 = in8;            int8_t* tab8 = in8 + QK2;
    __half* v1t2 = vt2;            __half* v2t2 = vt2 + (size_t)DC * 2 * NR;
    float*  S_1 = S;               float*  S_2 = S + (size_t)NR * NR;
    __half* P_1 = S2;              __half* P_2 = S2 + (size_t)NR * NR;

    // ---- launches 0-2: input conversions + combined weight prep ----
    const size_t tot = (size_t)NR * DC;
    convert_split<<<(unsigned)((tot / 4 + 255) / 256), 256>>>(img, img2, img8, DC, tot);
    convert_split<<<(unsigned)((tot / 4 + 255) / 256), 256>>>(tab, tab2, tab8, DC, tot);
    weight_prep<<<dim3(64, 64, 7), dim3(32, 8)>>>(
        Wqi, Wkt, Wvt, Wqt, Wki, Wvi, Wo,
        wqi2, wkt2, wvt2, wqt2, wki2, wvi2, wo2, w8);

    // ---- launch 3: all 4 Q/K projections (int8 corr + fp16 hi·hi + emit8) ----
    {
        GB4 b = {{ { img2, wqi2, img8, wqi8, bqi, nullptr, q12, q18 },
                   { tab2, wkt2, tab8, wkt8, bkt, nullptr, k12, k18 },
                   { tab2, wqt2, tab8, wqt8, bqt, nullptr, q22, q28 },
                   { img2, wki2, img8, wki8, bki, nullptr, k22, k28 } }};
        hgemm3<1,1,4,1><<<dim3(DC/128, NR/128, 4), TPB, GSMEM>>>(
            b, DC, 2*DC, 2*DC, 2*DC, 2*DC, DC, SCOMB_PROJ);
    }
    // ---- launch 4: both V^T projections (1-pass) ----
    {
        GB4 b = {{ { wvt2, tab2, nullptr, nullptr, bvt, nullptr, v1t2, nullptr },
                   { wvi2, img2, nullptr, nullptr, bvi, nullptr, v2t2, nullptr },
                   {}, {} }};
        hgemm3<1,2,1,0><<<dim3(NR/128, DC/128, 2), TPB, GSMEM>>>(
            b, DC, 2*DC, 2*DC, 0, 2*NR, NR, 0.0f);
    }
    // ---- launch 5: both QK^T (int8 corrections + fp16 hi·hi) — ncu target ----
    {
        GB4 b = {{ { q12, k12, q18, k18, nullptr, S_1, nullptr, nullptr },
                   { q22, k22, q28, k28, nullptr, S_2, nullptr, nullptr },
                   {}, {} }};
        hgemm3<0,0,4,0><<<dim3(NR/128, NR/128, 2), TPB, GSMEM>>>(
            b, DC, 2*DC, 2*DC, 2*DC, NR, 0, SCOMB_QK);
    }
    // ---- launch 6: both softmaxes ----
    softmax_hi<<<dim3(NR, 2), 256>>>(S, S2);
    // ---- launch 7: both P·V (1-pass) ----
    {
        GB4 b = {{ { P_1, v1t2, nullptr, nullptr, nullptr, nullptr, fused2 + DC, nullptr },
                   { P_2, v2t2, nullptr, nullptr, nullptr, nullptr, fused2, nullptr },
                   {}, {} }};
        hgemm3<1,0,1,0><<<dim3(DC/128, NR/128, 2), TPB, GSMEM>>>(
            b, NR, NR, 2*NR, 0, 4*DC, 2*DC, 0.0f);
    }
    // ---- launch 8: output projection (1-pass, fp32 out) ----
    {
        GB4 b = {{ { fused2, wo2, nullptr, nullptr, bo, out, nullptr, nullptr },
                   {}, {}, {} }};
        hgemm3<0,1,1,0><<<dim3(2*DC/128, NR/128, 1), TPB, GSMEM>>>(
            b, 2*DC, 4*DC, 4*DC, 0, 2*DC, 0, 0.0f);
    }
}

// round 12
// speedup vs baseline: 1.7274x; 1.0891x over previous
#include <cuda_runtime.h>
#include <cuda_fp16.h>
#include <cstdint>

#define NR 8192
#define DC 1024
#define PCAP 1024                    // sparse-P capacity per row
#define PTAU 1e-9f                   // normalized-prob threshold

// int8 scales (validated R10/R11)
#define S8_HI 32.0f
#define S8_LO 65536.0f
#define SCOMB_QK   (1.0f / 2097152.0f)     // 2^-21
#define SIN_HI 16.0f
#define SIN_LO 16384.0f
#define SW_HI  1024.0f
#define SW_LO  1048576.0f
#define SCOMB_PROJ (1.0f / 16777216.0f)    // 2^-24

// ---------------------------------------------------------------------------
// Static device scratch. Split-fp16 tensors stored [rows, 2K]: hi | lo.
// ---------------------------------------------------------------------------
__device__ float  g_S[(size_t)2 * NR * NR];             // logits (branch 0/1)
__device__ __half g_img2[(size_t)NR * 2 * DC];
__device__ __half g_tab2[(size_t)NR * 2 * DC];
__device__ int8_t g_in8[(size_t)2 * NR * 2 * DC];       // img8, tab8 (hi|lo)
__device__ __half g_w2[(size_t)6 * DC * 2 * DC];        // 6x W^T [1024,2048]
__device__ int8_t g_w8[(size_t)6 * DC * 2 * DC];        // 6x W^T int8 (hi|lo)
__device__ __half g_wo2[(size_t)2 * DC * 4 * DC];       // Wo^T [2048,4096]
__device__ __half g_qk2[(size_t)4 * NR * 2 * DC];       // q1,k1,q2,k2 fp16 hi|lo
__device__ int8_t g_qk8[(size_t)4 * NR * 2 * DC];       // q1,k1,q2,k2 int8 hi|lo
__device__ __half g_v2[(size_t)2 * NR * 2 * DC];        // v1,v2 row-major hi|lo
__device__ int    g_Pidx[(size_t)2 * NR * PCAP];        // sparse P indices
__device__ float  g_Pval[(size_t)2 * NR * PCAP];        // sparse P probs (fp32)
__device__ int    g_Pcnt[2 * NR];
__device__ __half g_fused2[(size_t)NR * 4 * DC];        // fused split [8192,4096]

// ---------------------------------------------------------------------------
// helpers
// ---------------------------------------------------------------------------
__device__ __forceinline__ uint32_t smem_u32(const void* p) {
    uint32_t a;
    asm("{ .reg .u64 t; cvta.to.shared.u64 t, %1; cvt.u32.u64 %0, t; }" : "=r"(a) : "l"(p));
    return a;
}
__device__ __forceinline__ void cp16(uint32_t d, const void* g) {
    asm volatile("cp.async.cg.shared.global [%0], [%1], 16;"
                 :: "r"(d), "l"(__cvta_generic_to_global(g)) : "memory");
}
__device__ __forceinline__ void ldm4(uint32_t* r, uint32_t a) {
    asm volatile("ldmatrix.sync.aligned.m8n8.x4.shared.b16 {%0,%1,%2,%3}, [%4];"
                 : "=r"(r[0]), "=r"(r[1]), "=r"(r[2]), "=r"(r[3]) : "r"(a));
}
__device__ __forceinline__ void mma16816(float* d, const uint32_t* a, const uint32_t* b) {
    asm("mma.sync.aligned.m16n8k16.row.col.f32.f16.f16.f32 "
        "{%0,%1,%2,%3}, {%4,%5,%6,%7}, {%8,%9}, {%0,%1,%2,%3};"
        : "+f"(d[0]), "+f"(d[1]), "+f"(d[2]), "+f"(d[3])
        : "r"(a[0]), "r"(a[1]), "r"(a[2]), "r"(a[3]), "r"(b[0]), "r"(b[1]));
}
__device__ __forceinline__ void mma16832s8(int* d, const uint32_t* a, const uint32_t* b) {
    asm("mma.sync.aligned.m16n8k32.row.col.s32.s8.s8.s32 "
        "{%0,%1,%2,%3}, {%4,%5,%6,%7}, {%8,%9}, {%0,%1,%2,%3};"
        : "+r"(d[0]), "+r"(d[1]), "+r"(d[2]), "+r"(d[3])
        : "r"(a[0]), "r"(a[1]), "r"(a[2]), "r"(a[3]), "r"(b[0]), "r"(b[1]));
}
__device__ __forceinline__ __half2 split_hi(float x0, float x1, __half2& lo) {
    __half h0 = __float2half_rn(x0), h1 = __float2half_rn(x1);
    lo = __halves2half2(__float2half_rn(x0 - __half2float(h0)),
                        __float2half_rn(x1 - __half2float(h1)));
    return __halves2half2(h0, h1);
}
__device__ __forceinline__ int8_t q8clamp(float x, float s) {
    int v = __float2int_rn(x * s);
    v = v > 127 ? 127 : (v < -127 ? -127 : v);
    return (int8_t)v;
}

// ---------------------------------------------------------------------------
// Batched split NT GEMM (validated R11 core):  C = A . B^T per blockIdx.z
// PASSES=4: int8 corrections (2 sweeps, shared s32 acc) + fp16 hi·hi (fp32 acc)
// PASSES=1: hi·hi only.
// ---------------------------------------------------------------------------
#define TPB 256
#define AST 144
#define STG (128 * AST * 2)
#define GSMEM (3 * STG)

struct GB { const __half* A; const __half* B; const int8_t* A8; const int8_t* B8;
            const float* bias; float* Cf; __half* Ch; int8_t* C8; };
struct GB4 { GB g[4]; };

template <int OUT_MODE, int BIAS, int PASSES, int EMIT8>
__global__ __launch_bounds__(TPB, 2)
void hgemm3(const __grid_constant__ GB4 batch, int K,
            size_t ldA, size_t ldB, size_t ld8, int ldc, int lo_off, float s_comb)
{
    extern __shared__ char smc[];
    const uint32_t sb = smem_u32(smc);
    const GB gb = batch.g[blockIdx.z];
    const int tid = threadIdx.x;
    const int wid = tid >> 5, lane = tid & 31;
    const int g = lane >> 2, t = lane & 3;
    const int wm = wid & 1, wn = wid >> 1;
    const int m0 = blockIdx.y * 128, n0 = blockIdx.x * 128;

    const int K64 = K >> 6;
    const int corr  = (PASSES == 4) ? K64 : 0;
    const int total = corr + K64;

    const int lr = tid >> 3;
    const int lc  = (tid & 7) * 8;
    const int lcB = (tid & 7) * 16;

    auto load_stage = [&](int s, int step) {
        if (step < total) {
            const uint32_t da = sb + s * STG + lr * AST + lcB;
            const uint32_t db = da + 128 * AST;
            if (PASSES == 4 && step < corr) {
                const int spw = K >> 7;
                const int swp = step / spw, kk = step - swp * spw;
                const int a8o = swp ? K : 0;
                const int b8o = swp ? 0 : K;
                const int8_t* ga  = gb.A8 + (size_t)(m0 + lr) * ld8 + a8o + kk * 128 + lcB;
                const int8_t* gbp = gb.B8 + (size_t)(n0 + lr) * ld8 + b8o + kk * 128 + lcB;
#pragma unroll
                for (int i = 0; i < 4; ++i) {
                    cp16(da + i * 32 * AST, ga  + (size_t)i * 32 * ld8);
                    cp16(db + i * 32 * AST, gbp + (size_t)i * 32 * ld8);
                }
            } else {
                const int kk = step - corr;
                const __half* ga  = gb.A + (size_t)(m0 + lr) * ldA + (size_t)kk * 64 + lc;
                const __half* gbp = gb.B + (size_t)(n0 + lr) * ldB + (size_t)kk * 64 + lc;
#pragma unroll
                for (int i = 0; i < 4; ++i) {
                    cp16(da + i * 32 * AST, ga  + (size_t)i * 32 * ldA);
                    cp16(db + i * 32 * AST, gbp + (size_t)i * 32 * ldB);
                }
            }
        }
        asm volatile("cp.async.commit_group;" ::: "memory");
    };

    const uint32_t aoff = (uint32_t)(wm * 64 + (lane & 15)) * AST + ((lane >> 4) << 4);
    const uint32_t boff = 128 * AST +
        (uint32_t)(wn * 32 + ((lane & 7) | ((lane >> 1) & 8))) * AST +
        (((lane >> 3) & 1) << 4);

    load_stage(0, 0);
    load_stage(1, 1);

    int iacc[4][4][4];
    if (PASSES == 4) {
#pragma unroll
        for (int i = 0; i < 4; ++i)
#pragma unroll
            for (int j = 0; j < 4; ++j)
#pragma unroll
                for (int r = 0; r < 4; ++r) iacc[i][j][r] = 0;
    }

    for (int step = 0; step < corr; ++step) {
        asm volatile("cp.async.wait_group 1;" ::: "memory");
        __syncthreads();
        load_stage((step + 2) % 3, step + 2);
        const uint32_t sbase = sb + (step % 3) * STG;
#pragma unroll
        for (int kh = 0; kh < 4; ++kh) {
            const uint32_t ko = kh * 32;
            uint32_t af[4][4], bf[4][2];
#pragma unroll
            for (int mt = 0; mt < 4; ++mt)
                ldm4(af[mt], sbase + aoff + (uint32_t)mt * 16 * AST + ko);
#pragma unroll
            for (int np = 0; np < 2; ++np) {
                uint32_t r[4];
                ldm4(r, sbase + boff + (uint32_t)np * 16 * AST + ko);
                bf[np * 2][0] = r[0];      bf[np * 2][1] = r[1];
                bf[np * 2 + 1][0] = r[2];  bf[np * 2 + 1][1] = r[3];
            }
#pragma unroll
            for (int mt = 0; mt < 4; ++mt)
#pragma unroll
                for (int nt = 0; nt < 4; ++nt)
                    mma16832s8(iacc[mt][nt], af[mt], bf[nt]);
        }
    }

    float acc[4][4][4];
#pragma unroll
    for (int i = 0; i < 4; ++i)
#pragma unroll
        for (int j = 0; j < 4; ++j) {
            if (PASSES == 4) {
#pragma unroll
                for (int r = 0; r < 4; ++r)
                    acc[i][j][r] = (float)iacc[i][j][r] * s_comb;
            } else {
#pragma unroll
                for (int r = 0; r < 4; ++r) acc[i][j][r] = 0.0f;
            }
        }

    for (int step = corr; step < total; ++step) {
        asm volatile("cp.async.wait_group 1;" ::: "memory");
        __syncthreads();
        load_stage((step + 2) % 3, step + 2);
        const uint32_t sbase = sb + (step % 3) * STG;
#pragma unroll
        for (int kh = 0; kh < 4; ++kh) {
            const uint32_t ko = kh * 32;
            uint32_t af[4][4], bf[4][2];
#pragma unroll
            for (int mt = 0; mt < 4; ++mt)
                ldm4(af[mt], sbase + aoff + (uint32_t)mt * 16 * AST + ko);
#pragma unroll
            for (int np = 0; np < 2; ++np) {
                uint32_t r[4];
                ldm4(r, sbase + boff + (uint32_t)np * 16 * AST + ko);
                bf[np * 2][0] = r[0];      bf[np * 2][1] = r[1];
                bf[np * 2 + 1][0] = r[2];  bf[np * 2 + 1][1] = r[3];
            }
#pragma unroll
            for (int mt = 0; mt < 4; ++mt)
#pragma unroll
                for (int nt = 0; nt < 4; ++nt)
                    mma16816(acc[mt][nt], af[mt], bf[nt]);
        }
    }

    // ---- epilogue ----
#pragma unroll
    for (int mt = 0; mt < 4; ++mt) {
        const int r0 = m0 + wm * 64 + mt * 16 + g;
        const int r1 = r0 + 8;
#pragma unroll
        for (int nt = 0; nt < 4; ++nt) {
            const int col = n0 + wn * 32 + nt * 8 + 2 * t;
            float v00 = acc[mt][nt][0], v01 = acc[mt][nt][1];
            float v10 = acc[mt][nt][2], v11 = acc[mt][nt][3];
            if (BIAS == 1) {
                const float b0 = gb.bias[col], b1 = gb.bias[col + 1];
                v00 += b0; v01 += b1; v10 += b0; v11 += b1;
            } else if (BIAS == 2) {
                const float b0 = gb.bias[r0], b1 = gb.bias[r1];
                v00 += b0; v01 += b0; v10 += b1; v11 += b1;
            }
            if (OUT_MODE == 0) {
                *reinterpret_cast<float2*>(&gb.Cf[(size_t)r0 * ldc + col]) = make_float2(v00, v01);
                *reinterpret_cast<float2*>(&gb.Cf[(size_t)r1 * ldc + col]) = make_float2(v10, v11);
            } else {
                __half2 lo0, lo1;
                __half2 hi0 = split_hi(v00, v01, lo0);
                __half2 hi1 = split_hi(v10, v11, lo1);
                __half2* p0 = reinterpret_cast<__half2*>(&gb.Ch[(size_t)r0 * ldc + col]);
                __half2* p1 = reinterpret_cast<__half2*>(&gb.Ch[(size_t)r1 * ldc + col]);
                p0[0] = hi0;  p0[lo_off / 2] = lo0;
                p1[0] = hi1;  p1[lo_off / 2] = lo1;
                if (EMIT8) {
                    const float l00 = __low2float(lo0), l01 = __high2float(lo0);
                    const float l10 = __low2float(lo1), l11 = __high2float(lo1);
                    char2 h8a = { q8clamp(v00, S8_HI), q8clamp(v01, S8_HI) };
                    char2 h8b = { q8clamp(v10, S8_HI), q8clamp(v11, S8_HI) };
                    char2 l8a = { q8clamp(l00, S8_LO), q8clamp(l01, S8_LO) };
                    char2 l8b = { q8clamp(l10, S8_LO), q8clamp(l11, S8_LO) };
                    *reinterpret_cast<char2*>(&gb.C8[(size_t)r0 * ldc + col])          = h8a;
                    *reinterpret_cast<char2*>(&gb.C8[(size_t)r1 * ldc + col])          = h8b;
                    *reinterpret_cast<char2*>(&gb.C8[(size_t)r0 * ldc + lo_off + col]) = l8a;
                    *reinterpret_cast<char2*>(&gb.C8[(size_t)r1 * ldc + lo_off + col]) = l8b;
                }
            }
        }
    }
}

// ---------------------------------------------------------------------------
// fp32 [R,C] -> split fp16 [R,2C] + int8 [R,2C]
// ---------------------------------------------------------------------------
__global__ __launch_bounds__(256)
void convert_split(const float* __restrict__ in, __half* __restrict__ out,
                   int8_t* __restrict__ out8, int C, size_t total)
{
    size_t i = ((size_t)blockIdx.x * 256 + threadIdx.x) * 4;
    if (i >= total) return;
    float4 v = *reinterpret_cast<const float4*>(&in[i]);
    size_t r = i / C;
    int c = (int)(i - r * C);
    __half2 lo0, lo1;
    __half2 hi0 = split_hi(v.x, v.y, lo0);
    __half2 hi1 = split_hi(v.z, v.w, lo1);
    __half* row = out + r * (2 * (size_t)C);
    *reinterpret_cast<__half2*>(&row[c])         = hi0;
    *reinterpret_cast<__half2*>(&row[c + 2])     = hi1;
    *reinterpret_cast<__half2*>(&row[C + c])     = lo0;
    *reinterpret_cast<__half2*>(&row[C + c + 2]) = lo1;
    int8_t* row8 = out8 + r * (2 * (size_t)C);
    char4 h8 = { q8clamp(__low2float(hi0), SIN_HI), q8clamp(__high2float(hi0), SIN_HI),
                 q8clamp(__low2float(hi1), SIN_HI), q8clamp(__high2float(hi1), SIN_HI) };
    char4 l8 = { q8clamp(__low2float(lo0), SIN_LO), q8clamp(__high2float(lo0), SIN_LO),
                 q8clamp(__low2float(lo1), SIN_LO), q8clamp(__high2float(lo1), SIN_LO) };
    *reinterpret_cast<char4*>(&row8[c])     = h8;
    *reinterpret_cast<char4*>(&row8[C + c]) = l8;
}

// ---------------------------------------------------------------------------
// All 7 weight transposes in ONE launch (+ int8 for projection weights)
// ---------------------------------------------------------------------------
__global__ __launch_bounds__(256)
void weight_prep(const float* w0, const float* w1, const float* w2c,
                 const float* w3, const float* w4, const float* w5,
                 const float* w6,
                 __half* o0, __half* o1, __half* o2, __half* o3,
                 __half* o4, __half* o5, __half* o6, int8_t* o8base)
{
    const float* src; __half* dst; int R, C;
    switch (blockIdx.z) {
        case 0: src = w0; dst = o0; R = DC; C = DC; break;
        case 1: src = w1; dst = o1; R = DC; C = DC; break;
        case 2: src = w2c; dst = o2; R = DC; C = DC; break;
        case 3: src = w3; dst = o3; R = DC; C = DC; break;
        case 4: src = w4; dst = o4; R = DC; C = DC; break;
        case 5: src = w5; dst = o5; R = DC; C = DC; break;
        default: src = w6; dst = o6; R = 2 * DC; C = 2 * DC; break;
    }
    const int bx = blockIdx.x * 32, by = blockIdx.y * 32;
    if (bx >= C || by >= R) return;
    int8_t* dst8 = (blockIdx.z < 6)
        ? o8base + (size_t)blockIdx.z * DC * 2 * DC : nullptr;

    __shared__ float tl[32][33];
    const int tx = threadIdx.x, ty = threadIdx.y;
#pragma unroll
    for (int j = ty; j < 32; j += 8)
        tl[j][tx] = src[(size_t)(by + j) * C + bx + tx];
    __syncthreads();
#pragma unroll
    for (int j = ty; j < 32; j += 8) {
        const float v = tl[tx][j];
        const __half h = __float2half_rn(v);
        const float hf = __half2float(h);
        const __half l = __float2half_rn(v - hf);
        __half* row = dst + (size_t)(bx + j) * (2 * (size_t)R);
        row[by + tx]     = h;
        row[R + by + tx] = l;
        if (dst8) {
            int8_t* row8 = dst8 + (size_t)(bx + j) * (2 * (size_t)R);
            row8[by + tx]     = q8clamp(hf, SW_HI);
            row8[R + by + tx] = q8clamp(__half2float(l), SW_LO);
        }
    }
}

// ---------------------------------------------------------------------------
// Row softmax + deterministic in-order sparse compaction.
// One block per (row, branch). Emits (idx, fp32 prob) for p > PTAU, <= PCAP.
// ---------------------------------------------------------------------------
__global__ __launch_bounds__(256)
void softmax_sparse(const float* __restrict__ S,
                    int* __restrict__ Pidx, float* __restrict__ Pval,
                    int* __restrict__ Pcnt)
{
    __shared__ float row[NR];
    __shared__ float red[256];
    __shared__ int   scn[256];
    __shared__ int   lidx[PCAP];
    __shared__ float lp[PCAP];
    __shared__ int   ltot;

    const int br = blockIdx.y;
    const size_t soff = (size_t)br * NR * NR + (size_t)blockIdx.x * NR;
    const float* p = S + soff;
    const int tid = threadIdx.x;

    float lmax = -3.0e38f;
    for (int i = tid * 4; i < NR; i += 1024) {
        float4 v = *reinterpret_cast<const float4*>(&p[i]);
        *reinterpret_cast<float4*>(&row[i]) = v;
        lmax = fmaxf(lmax, fmaxf(fmaxf(v.x, v.y), fmaxf(v.z, v.w)));
    }
    red[tid] = lmax;
    __syncthreads();
#pragma unroll
    for (int s = 128; s > 0; s >>= 1) {
        if (tid < s) red[tid] = fmaxf(red[tid], red[tid + s]);
        __syncthreads();
    }
    const float bmax = red[0];
    __syncthreads();

    float lsum = 0.0f;
    for (int i = tid * 4; i < NR; i += 1024) {
        float4 v = *reinterpret_cast<float4*>(&row[i]);
        v.x = __expf(v.x - bmax); v.y = __expf(v.y - bmax);
        v.z = __expf(v.z - bmax); v.w = __expf(v.w - bmax);
        lsum += v.x + v.y + v.z + v.w;
        *reinterpret_cast<float4*>(&row[i]) = v;
    }
    red[tid] = lsum;
    __syncthreads();
#pragma unroll
    for (int s = 128; s > 0; s >>= 1) {
        if (tid < s) red[tid] += red[tid + s];
        __syncthreads();
    }
    const float inv = 1.0f / red[0];
    if (tid == 0) ltot = 0;
    __syncthreads();

    // ---- in-order compaction, 1024 elements per chunk ----
    for (int base = 0; base < NR; base += 1024) {
        float4 v = *reinterpret_cast<const float4*>(&row[base + tid * 4]);
        float pe[4] = { v.x * inv, v.y * inv, v.z * inv, v.w * inv };
        int c = (pe[0] > PTAU) + (pe[1] > PTAU) + (pe[2] > PTAU) + (pe[3] > PTAU);
        scn[tid] = c;
        __syncthreads();
        // Hillis-Steele inclusive scan over 256 counts
#pragma unroll
        for (int s = 1; s < 256; s <<= 1) {
            int add = (tid >= s) ? scn[tid - s] : 0;
            __syncthreads();
            scn[tid] += add;
            __syncthreads();
        }
        int o = ltot + scn[tid] - c;        // exclusive offset
        const int chunk_total = scn[255];
#pragma unroll
        for (int e = 0; e < 4; ++e) {
            if (pe[e] > PTAU) {
                if (o < PCAP) { lidx[o] = base + tid * 4 + e; lp[o] = pe[e]; }
                ++o;
            }
        }
        __syncthreads();
        if (tid == 0) ltot += chunk_total;
        __syncthreads();
    }

    const int cnt = ltot < PCAP ? ltot : PCAP;
    const size_t loff = ((size_t)br * NR + blockIdx.x) * PCAP;
    for (int i = tid; i < cnt; i += 256) {
        Pidx[loff + i] = lidx[i];
        Pval[loff + i] = lp[i];
    }
    if (tid == 0) Pcnt[br * NR + blockIdx.x] = cnt;
}

// ---------------------------------------------------------------------------
// Sparse P·V: one block per (row, branch). out[d] = sum_j p_j * Vhi[idx_j][d].
// Deterministic (fixed j order). Writes fused2 split fp16 directly.
// ---------------------------------------------------------------------------
__global__ __launch_bounds__(256)
void sparse_pv(const int* __restrict__ Pidx, const float* __restrict__ Pval,
               const int* __restrict__ Pcnt, const __half* __restrict__ v2,
               __half* __restrict__ fused2)
{
    __shared__ int   sidx[128];
    __shared__ float sval[128];
    const int rowi = blockIdx.x, br = blockIdx.y;
    const size_t loff = ((size_t)br * NR + rowi) * PCAP;
    const int cnt = Pcnt[br * NR + rowi];
    const __half* V = v2 + (size_t)br * NR * 2 * DC;   // [8192, 2DC] hi|lo
    const int tid = threadIdx.x;
    const int d = tid * 4;

    float a0 = 0.f, a1 = 0.f, a2 = 0.f, a3 = 0.f;
    for (int base = 0; base < cnt; base += 128) {
        const int n = min(128, cnt - base);
        if (tid < n) { sidx[tid] = Pidx[loff + base + tid]; sval[tid] = Pval[loff + base + tid]; }
        __syncthreads();
#pragma unroll 4
        for (int j = 0; j < n; ++j) {
            const float pj = sval[j];
            const __half* vr = V + (size_t)sidx[j] * (2 * DC) + d;
            const __half2 h0 = *reinterpret_cast<const __half2*>(vr);
            const __half2 h1 = *reinterpret_cast<const __half2*>(vr + 2);
            a0 = fmaf(pj, __low2float(h0), a0);
            a1 = fmaf(pj, __high2float(h0), a1);
            a2 = fmaf(pj, __low2float(h1), a2);
            a3 = fmaf(pj, __high2float(h1), a3);
        }
        __syncthreads();
    }

    // branch 0 -> attended_tabular -> fused cols [DC, 2DC); branch 1 -> [0, DC)
    const int col = (br == 0 ? DC : 0) + d;
    __half2 lo0, lo1;
    __half2 hi0 = split_hi(a0, a1, lo0);
    __half2 hi1 = split_hi(a2, a3, lo1);
    __half* frow = fused2 + (size_t)rowi * 4 * DC;
    *reinterpret_cast<__half2*>(&frow[col])              = hi0;
    *reinterpret_cast<__half2*>(&frow[col + 2])          = hi1;
    *reinterpret_cast<__half2*>(&frow[2 * DC + col])     = lo0;
    *reinterpret_cast<__half2*>(&frow[2 * DC + col + 2]) = lo1;
}

// ---------------------------------------------------------------------------
// Launch sequence
// ---------------------------------------------------------------------------
extern "C" void kernel_launch(void* const* d_in, const int* in_sizes, int n_in,
                              void* d_out, int out_size)
{
    const float* img = (const float*)d_in[0];
    const float* tab = (const float*)d_in[1];
    const float* Wqi = (const float*)d_in[2];  const float* bqi = (const float*)d_in[3];
    const float* Wkt = (const float*)d_in[4];  const float* bkt = (const float*)d_in[5];
    const float* Wvt = (const float*)d_in[6];  const float* bvt = (const float*)d_in[7];
    const float* Wqt = (const float*)d_in[8];  const float* bqt = (const float*)d_in[9];
    const float* Wki = (const float*)d_in[10]; const float* bki = (const float*)d_in[11];
    const float* Wvi = (const float*)d_in[12]; const float* bvi = (const float*)d_in[13];
    const float* Wo  = (const float*)d_in[14]; const float* bo  = (const float*)d_in[15];
    float* out = (float*)d_out;

    cudaFuncSetAttribute(hgemm3<0,0,4,0>, cudaFuncAttributeMaxDynamicSharedMemorySize, GSMEM);
    cudaFuncSetAttribute(hgemm3<0,1,1,0>, cudaFuncAttributeMaxDynamicSharedMemorySize, GSMEM);
    cudaFuncSetAttribute(hgemm3<1,1,1,0>, cudaFuncAttributeMaxDynamicSharedMemorySize, GSMEM);
    cudaFuncSetAttribute(hgemm3<1,1,4,1>, cudaFuncAttributeMaxDynamicSharedMemorySize, GSMEM);

    float *S, *Pval;
    __half *img2, *tab2, *w2, *wo2, *qk2, *v2, *fused2;
    int8_t *qk8, *in8, *w8;
    int *PidxP, *PcntP;
    cudaGetSymbolAddress((void**)&S,      g_S);
    cudaGetSymbolAddress((void**)&img2,   g_img2);
    cudaGetSymbolAddress((void**)&tab2,   g_tab2);
    cudaGetSymbolAddress((void**)&in8,    g_in8);
    cudaGetSymbolAddress((void**)&w2,     g_w2);
    cudaGetSymbolAddress((void**)&w8,     g_w8);
    cudaGetSymbolAddress((void**)&wo2,    g_wo2);
    cudaGetSymbolAddress((void**)&qk2,    g_qk2);
    cudaGetSymbolAddress((void**)&qk8,    g_qk8);
    cudaGetSymbolAddress((void**)&v2,     g_v2);
    cudaGetSymbolAddress((void**)&PidxP,  g_Pidx);
    cudaGetSymbolAddress((void**)&Pval,   g_Pval);
    cudaGetSymbolAddress((void**)&PcntP,  g_Pcnt);
    cudaGetSymbolAddress((void**)&fused2, g_fused2);

    const size_t W2SZ = (size_t)DC * 2 * DC;
    __half* wqi2 = w2 + 0 * W2SZ;  __half* wkt2 = w2 + 1 * W2SZ;
    __half* wvt2 = w2 + 2 * W2SZ;  __half* wqt2 = w2 + 3 * W2SZ;
    __half* wki2 = w2 + 4 * W2SZ;  __half* wvi2 = w2 + 5 * W2SZ;
    int8_t* wqi8 = w8 + 0 * W2SZ;  int8_t* wkt8 = w8 + 1 * W2SZ;
    int8_t* wqt8 = w8 + 3 * W2SZ;  int8_t* wki8 = w8 + 4 * W2SZ;
    const size_t QK2 = (size_t)NR * 2 * DC;
    __half* q12 = qk2 + 0 * QK2;   __half* k12 = qk2 + 1 * QK2;
    __half* q22 = qk2 + 2 * QK2;   __half* k22 = qk2 + 3 * QK2;
    int8_t* q18 = qk8 + 0 * QK2;   int8_t* k18 = qk8 + 1 * QK2;
    int8_t* q28 = qk8 + 2 * QK2;   int8_t* k28 = qk8 + 3 * QK2;
    int8_t* img8 = in8;            int8_t* tab8 = in8 + QK2;
    __half* v1r = v2;              __half* v2r = v2 + QK2;   // row-major v, hi|lo
    float*  S_1 = S;               float*  S_2 = S + (size_t)NR * NR;

    // ---- launches 0-2: input conversions + combined weight prep ----
    const size_t tot = (size_t)NR * DC;
    convert_split<<<(unsigned)((tot / 4 + 255) / 256), 256>>>(img, img2, img8, DC, tot);
    convert_split<<<(unsigned)((tot / 4 + 255) / 256), 256>>>(tab, tab2, tab8, DC, tot);
    weight_prep<<<dim3(64, 64, 7), dim3(32, 8)>>>(
        Wqi, Wkt, Wvt, Wqt, Wki, Wvi, Wo,
        wqi2, wkt2, wvt2, wqt2, wki2, wvi2, wo2, w8);

    // ---- launch 3: all 4 Q/K projections (int8 corr + fp16 hi·hi + emit8) ----
    {
        GB4 b = {{ { img2, wqi2, img8, wqi8, bqi, nullptr, q12, q18 },
                   { tab2, wkt2, tab8, wkt8, bkt, nullptr, k12, k18 },
                   { tab2, wqt2, tab8, wqt8, bqt, nullptr, q22, q28 },
                   { img2, wki2, img8, wki8, bki, nullptr, k22, k28 } }};
        hgemm3<1,1,4,1><<<dim3(DC/128, NR/128, 4), TPB, GSMEM>>>(
            b, DC, 2*DC, 2*DC, 2*DC, 2*DC, DC, SCOMB_PROJ);
    }
    // ---- launch 4: both V projections (row-major, 1-pass, per-col bias) ----
    {
        GB4 b = {{ { tab2, wvt2, nullptr, nullptr, bvt, nullptr, v1r, nullptr },
                   { img2, wvi2, nullptr, nullptr, bvi, nullptr, v2r, nullptr },
                   {}, {} }};
        hgemm3<1,1,1,0><<<dim3(DC/128, NR/128, 2), TPB, GSMEM>>>(
            b, DC, 2*DC, 2*DC, 0, 2*DC, DC, 0.0f);
    }
    // ---- launch 5: both QK^T (int8 corrections + fp16 hi·hi) — ncu target ----
    {
        GB4 b = {{ { q12, k12, q18, k18, nullptr, S_1, nullptr, nullptr },
                   { q22, k22, q28, k28, nullptr, S_2, nullptr, nullptr },
                   {}, {} }};
        hgemm3<0,0,4,0><<<dim3(NR/128, NR/128, 2), TPB, GSMEM>>>(
            b, DC, 2*DC, 2*DC, 2*DC, NR, 0, SCOMB_QK);
    }
    // ---- launch 6: softmax + sparse compaction (both branches) ----
    softmax_sparse<<<dim3(NR, 2), 256>>>(S, PidxP, Pval, PcntP);
    // ---- launch 7: sparse P·V (both branches) ----
    sparse_pv<<<dim3(NR, 2), 256>>>(PidxP, Pval, PcntP, v2, fused2);
    // ---- launch 8: output projection (1-pass, fp32 out) ----
    {
        GB4 b = {{ { fused2, wo2, nullptr, nullptr, bo, out, nullptr, nullptr },
                   {}, {}, {} }};
        hgemm3<0,1,1,0><<<dim3(2*DC/128, NR/128, 1), TPB, GSMEM>>>(
            b, 2*DC, 4*DC, 4*DC, 0, 2*DC, 0, 0.0f);
    }
}